// round 2
// baseline (speedup 1.0000x reference)
#include <cuda_runtime.h>
#include <math.h>

#define BATCH   262144
#define NNODES  1000000
#define DD      100
#define KP      416   // padded K: 100+100+4+100(t_enc)+100(h)=404 -> 416
#define NP      448   // padded N: 400 -> 448
#define NG      400   // real gate width

// -------- device scratch (allocation-free per harness rules) --------
__device__ float g_XC[(size_t)BATCH * KP];   // assembled input rows [BATCH][416]
__device__ float g_G [(size_t)BATCH * NG];   // gate pre-activations [BATCH][400]
__device__ float g_A [(size_t)BATCH * 64];   // relu(h_new @ W1^T + b1)
__device__ float g_WC[(size_t)NP * KP];      // combined weights [448][416]
__device__ float g_bc[NP];                   // combined bias
__device__ float g_stats[128];               // sum[64], sumsq[64]
__device__ float g_W2e[128];                 // folded W2 [64][2]
__device__ float g_be[2];                    // folded bias

// ===================== K0: prep combined weights, zero stats =====================
__global__ __launch_bounds__(256) void prep_kernel(const float* __restrict__ W_ih,
                                                   const float* __restrict__ W_hh,
                                                   const float* __restrict__ b_ih,
                                                   const float* __restrict__ b_hh) {
    int idx = blockIdx.x * 256 + threadIdx.x;
    if (idx < NP * KP) {
        int r = idx / KP, k = idx % KP;
        float v = 0.f;
        if (r < 200) {
            if (k < 304)       v = W_ih[r * 304 + k];
            else if (k < 404)  v = W_hh[r * 100 + (k - 304)];
        } else if (r < 300) {
            if (k < 304)       v = W_ih[r * 304 + k];
        } else if (r < 400) {
            if (k >= 304 && k < 404) v = W_hh[(r - 100) * 100 + (k - 304)];
        }
        g_WC[idx] = v;
    }
    if (idx < NP) {
        float bv = 0.f;
        if (idx < 200)      bv = b_ih[idx] + b_hh[idx];
        else if (idx < 300) bv = b_ih[idx];
        else if (idx < 400) bv = b_hh[idx - 100];
        g_bc[idx] = bv;
    }
    if (idx < 128) g_stats[idx] = 0.f;
}

// ===================== K1: gather + assemble X rows =====================
// one warp per row; 8 rows per 256-thread block
__global__ __launch_bounds__(256) void assemble_kernel(const int*   __restrict__ n_id,
                                                       const float* __restrict__ memory,
                                                       const int*   __restrict__ last_update,
                                                       const int*   __restrict__ store_src,
                                                       const int*   __restrict__ store_dst,
                                                       const int*   __restrict__ store_t,
                                                       const float* __restrict__ store_msg,
                                                       const float* __restrict__ time_w,
                                                       const float* __restrict__ time_b) {
    int w    = threadIdx.x >> 5;
    int lane = threadIdx.x & 31;
    int b = blockIdx.x * 8 + w;
    int n   = n_id[b];
    int src = store_src[n];
    int dst = store_dst[n];
    float dt = (float)(store_t[n] - last_update[n]);
    float*       xr = g_XC + (size_t)b * KP;
    const float* ms = memory + (size_t)src * DD;
    const float* md = memory + (size_t)dst * DD;
    const float* mn = memory + (size_t)n   * DD;
    #pragma unroll
    for (int c = lane; c < KP; c += 32) {
        float v;
        if (c < 100)      v = ms[c];
        else if (c < 200) v = md[c - 100];
        else if (c < 204) v = store_msg[(size_t)n * 4 + (c - 200)];
        else if (c < 304) {
            int j = c - 204;
            // match jax's mul-then-add rounding (no fma) — dt is large
            float arg = __fadd_rn(__fmul_rn(dt, time_w[j]), time_b[j]);
            v = cosf(arg);
        }
        else if (c < 404) v = mn[c - 304];
        else              v = 0.f;
        xr[c] = v;
    }
}

// ===================== K2: big GEMM  G = XC @ WC^T + bc =====================
// BM=128, BN=64, BK=16, 256 threads, 8x4 per thread
__global__ __launch_bounds__(256) void gemm_kernel() {
    __shared__ float As[16][128];
    __shared__ float Bs[16][64];
    const int m0  = blockIdx.x * 128;
    const int n0  = blockIdx.y * 64;
    const int tid = threadIdx.x;
    const int tx  = tid & 15;   // N dir
    const int ty  = tid >> 4;   // M dir

    float acc[8][4];
    #pragma unroll
    for (int i = 0; i < 8; i++)
        #pragma unroll
        for (int j = 0; j < 4; j++) acc[i][j] = 0.f;

    const float* Abase = g_XC + (size_t)m0 * KP;
    const float* Bbase = g_WC + (size_t)n0 * KP;

    for (int k0 = 0; k0 < KP; k0 += 16) {
        // load A tile 128x16 (2 float4 per thread), store k-major
        #pragma unroll
        for (int i = 0; i < 2; i++) {
            int lin = tid + i * 256;
            int row = lin >> 2;
            int kq  = (lin & 3) * 4;
            float4 v = *(const float4*)(Abase + (size_t)row * KP + k0 + kq);
            As[kq + 0][row] = v.x; As[kq + 1][row] = v.y;
            As[kq + 2][row] = v.z; As[kq + 3][row] = v.w;
        }
        // load B tile 64x16 (1 float4 per thread)
        {
            int row = tid >> 2;
            int kq  = (tid & 3) * 4;
            float4 v = *(const float4*)(Bbase + (size_t)row * KP + k0 + kq);
            Bs[kq + 0][row] = v.x; Bs[kq + 1][row] = v.y;
            Bs[kq + 2][row] = v.z; Bs[kq + 3][row] = v.w;
        }
        __syncthreads();
        #pragma unroll
        for (int k = 0; k < 16; k++) {
            float a[8], bb[4];
            #pragma unroll
            for (int i = 0; i < 8; i++) a[i] = As[k][ty * 8 + i];
            #pragma unroll
            for (int j = 0; j < 4; j++) bb[j] = Bs[k][tx * 4 + j];
            #pragma unroll
            for (int i = 0; i < 8; i++)
                #pragma unroll
                for (int j = 0; j < 4; j++)
                    acc[i][j] = fmaf(a[i], bb[j], acc[i][j]);
        }
        __syncthreads();
    }
    #pragma unroll
    for (int i = 0; i < 8; i++) {
        size_t m = (size_t)(m0 + ty * 8 + i);
        float* Crow = g_G + m * NG;
        #pragma unroll
        for (int j = 0; j < 4; j++) {
            int n = n0 + tx * 4 + j;
            if (n < NG) Crow[n] = acc[i][j] + g_bc[n];
        }
    }
}

// ===================== K3: GRU elementwise + W1 + BN stats =====================
// 256 threads = 8 warps; each warp handles 8 rows; 64 rows per block
__global__ __launch_bounds__(256) void gru_kernel(const float* __restrict__ W1,
                                                  const float* __restrict__ b1) {
    __shared__ float W1s[64 * 100];
    __shared__ __align__(16) float hns[8][100];
    __shared__ float sacc[64], qacc[64];
    int tid = threadIdx.x;
    for (int i = tid; i < 6400; i += 256) W1s[i] = W1[i];
    if (tid < 64)       sacc[tid] = 0.f;
    else if (tid < 128) qacc[tid - 64] = 0.f;
    __syncthreads();

    int w = tid >> 5, lane = tid & 31;
    float b1a = b1[lane], b1b = b1[lane + 32];
    float s0 = 0.f, q0 = 0.f, s1 = 0.f, q1 = 0.f;

    for (int t = 0; t < 8; t++) {
        int b = blockIdx.x * 64 + w * 8 + t;
        const float* Gr = g_G  + (size_t)b * NG;
        const float* hr = g_XC + (size_t)b * KP + 304;
        #pragma unroll
        for (int q = 0; q < 4; q++) {
            int d = lane + q * 32;
            if (d < 100) {
                float rr = 1.f / (1.f + __expf(-Gr[d]));
                float zz = 1.f / (1.f + __expf(-Gr[100 + d]));
                float nn = tanhf(Gr[200 + d] + rr * Gr[300 + d]);
                hns[w][d] = (1.f - zz) * nn + zz * hr[d];
            }
        }
        __syncwarp();
        float y0 = b1a, y1 = b1b;
        const float4* hv  = (const float4*)hns[w];
        const float4* wv0 = (const float4*)(W1s + lane * 100);
        const float4* wv1 = (const float4*)(W1s + (lane + 32) * 100);
        #pragma unroll
        for (int q = 0; q < 25; q++) {
            float4 h = hv[q], a = wv0[q], c = wv1[q];
            y0 += h.x * a.x + h.y * a.y + h.z * a.z + h.w * a.w;
            y1 += h.x * c.x + h.y * c.y + h.z * c.z + h.w * c.w;
        }
        float a0 = fmaxf(y0, 0.f), a1 = fmaxf(y1, 0.f);
        g_A[(size_t)b * 64 + lane]      = a0;
        g_A[(size_t)b * 64 + lane + 32] = a1;
        s0 += a0; q0 += a0 * a0;
        s1 += a1; q1 += a1 * a1;
        __syncwarp();
    }
    atomicAdd(&sacc[lane],      s0); atomicAdd(&qacc[lane],      q0);
    atomicAdd(&sacc[lane + 32], s1); atomicAdd(&qacc[lane + 32], q1);
    __syncthreads();
    if (tid < 64) {
        atomicAdd(&g_stats[tid],      sacc[tid]);
        atomicAdd(&g_stats[64 + tid], qacc[tid]);
    }
}

// ===================== K4: finalize BN, fold into W2 =====================
__global__ void finalize_kernel(const float* __restrict__ gamma,
                                const float* __restrict__ beta,
                                const float* __restrict__ W2,
                                const float* __restrict__ b2) {
    __shared__ float red0[64], red1[64];
    int j = threadIdx.x;  // 64 threads
    float mu  = g_stats[j]      * (1.f / BATCH);
    float var = g_stats[64 + j] * (1.f / BATCH) - mu * mu;
    float inv = rsqrtf(var + 1e-5f);
    float gsc = gamma[j] * inv;
    float w0 = W2[j], w1 = W2[64 + j];
    g_W2e[2 * j]     = w0 * gsc;
    g_W2e[2 * j + 1] = w1 * gsc;
    float c = beta[j] - mu * gsc;
    red0[j] = c * w0;
    red1[j] = c * w1;
    __syncthreads();
    if (j == 0) { float s = 0.f; for (int i = 0; i < 64; i++) s += red0[i]; g_be[0] = b2[0] + s; }
    if (j == 1) { float s = 0.f; for (int i = 0; i < 64; i++) s += red1[i]; g_be[1] = b2[1] + s; }
}

// ===================== K5: output = A @ W2e + be =====================
__global__ __launch_bounds__(256) void out_kernel(float* __restrict__ out) {
    __shared__ float w2s[128];
    __shared__ float bes[2];
    int tid = threadIdx.x;
    if (tid < 128) w2s[tid] = g_W2e[tid];
    if (tid < 2)   bes[tid] = g_be[tid];
    __syncthreads();
    int b = blockIdx.x * 256 + tid;
    const float4* ar = (const float4*)(g_A + (size_t)b * 64);
    float o0 = bes[0], o1 = bes[1];
    #pragma unroll
    for (int q = 0; q < 16; q++) {
        float4 v = ar[q];
        int j = q * 8;  // index into interleaved w2s (2 per channel)
        o0 += v.x * w2s[j]     + v.y * w2s[j + 2] + v.z * w2s[j + 4] + v.w * w2s[j + 6];
        o1 += v.x * w2s[j + 1] + v.y * w2s[j + 3] + v.z * w2s[j + 5] + v.w * w2s[j + 7];
    }
    ((float2*)out)[b] = make_float2(o0, o1);
}

// ===================== launcher =====================
extern "C" void kernel_launch(void* const* d_in, const int* in_sizes, int n_in,
                              void* d_out, int out_size) {
    const int*   n_id        = (const int*)  d_in[0];
    const float* memory      = (const float*)d_in[1];
    const int*   last_update = (const int*)  d_in[2];
    const int*   store_src   = (const int*)  d_in[3];
    const int*   store_dst   = (const int*)  d_in[4];
    const int*   store_t     = (const int*)  d_in[5];
    const float* store_msg   = (const float*)d_in[6];
    const float* time_w      = (const float*)d_in[7];
    const float* time_b      = (const float*)d_in[8];
    const float* W_ih        = (const float*)d_in[9];
    const float* b_ih        = (const float*)d_in[10];
    const float* W_hh        = (const float*)d_in[11];
    const float* b_hh        = (const float*)d_in[12];
    const float* W1          = (const float*)d_in[13];
    const float* b1          = (const float*)d_in[14];
    const float* gamma       = (const float*)d_in[15];
    const float* beta        = (const float*)d_in[16];
    const float* W2          = (const float*)d_in[17];
    const float* b2          = (const float*)d_in[18];
    float*       out         = (float*)d_out;

    prep_kernel<<<(NP * KP + 255) / 256, 256>>>(W_ih, W_hh, b_ih, b_hh);
    assemble_kernel<<<BATCH / 8, 256>>>(n_id, memory, last_update, store_src,
                                        store_dst, store_t, store_msg, time_w, time_b);
    gemm_kernel<<<dim3(BATCH / 128, NP / 64), 256>>>();
    gru_kernel<<<BATCH / 64, 256>>>(W1, b1);
    finalize_kernel<<<1, 64>>>(gamma, beta, W2, b2);
    out_kernel<<<BATCH / 256, 256>>>(out);
}

// round 4
// speedup vs baseline: 1.2001x; 1.2001x over previous
#include <cuda_runtime.h>
#include <cuda_bf16.h>
#include <math.h>
#include <stdint.h>

#define BATCH   262144
#define DD      100
#define KP      448       // padded K (bf16 cols): 404 -> 448
#define NP      400       // interleaved gate rows: 100 quadruples (r,z,n,hn)
#define BMM     128
#define BNN     80
#define NCHUNK  7         // 448/64

// -------- device scratch --------
__device__ __nv_bfloat16 g_Xhi[(size_t)BATCH * KP];
__device__ __nv_bfloat16 g_Xlo[(size_t)BATCH * KP];
__device__ __nv_bfloat16 g_Whi[(size_t)NP * KP];
__device__ __nv_bfloat16 g_Wlo[(size_t)NP * KP];
__device__ float g_bq[NP];
__device__ float g_HN[(size_t)BATCH * DD];     // h_new fp32
__device__ float g_A [(size_t)BATCH * 64];
__device__ float g_stats[128];
__device__ float g_W2e[128];
__device__ float g_be[2];

__device__ __forceinline__ uint32_t smem_u32(const void* p) {
    uint32_t a;
    asm("{ .reg .u64 t; cvta.to.shared.u64 t, %1; cvt.u32.u64 %0, t; }" : "=r"(a) : "l"(p));
    return a;
}
#define LDSM4(r, a) asm volatile("ldmatrix.sync.aligned.m8n8.x4.shared.b16 {%0,%1,%2,%3}, [%4];" \
    : "=r"((r)[0]), "=r"((r)[1]), "=r"((r)[2]), "=r"((r)[3]) : "r"(a))
#define LDSM2(r, a) asm volatile("ldmatrix.sync.aligned.m8n8.x2.shared.b16 {%0,%1}, [%2];" \
    : "=r"((r)[0]), "=r"((r)[1]) : "r"(a))
#define MMA(c, a, b) asm volatile( \
    "mma.sync.aligned.m16n8k16.row.col.f32.bf16.bf16.f32 {%0,%1,%2,%3},{%4,%5,%6,%7},{%8,%9},{%0,%1,%2,%3};" \
    : "+f"((c)[0]), "+f"((c)[1]), "+f"((c)[2]), "+f"((c)[3])                                                  \
    : "r"((a)[0]), "r"((a)[1]), "r"((a)[2]), "r"((a)[3]), "r"((b)[0]), "r"((b)[1]))

// smem layout (bytes) for gemm_kernel
#define SA_HI   0
#define SA_LO   16384
#define SB_HI   32768
#define SB_LO   43008
#define SBIAS   53248
#define SMEM_TOT 53568
// C staging reuses [0, 43008): 128 rows x 84 floats

// ===================== K0: prep interleaved split weights =====================
__global__ __launch_bounds__(256) void prep_kernel(const float* __restrict__ W_ih,
                                                   const float* __restrict__ W_hh,
                                                   const float* __restrict__ b_ih,
                                                   const float* __restrict__ b_hh) {
    int idx = blockIdx.x * 256 + threadIdx.x;
    if (idx < NP * KP) {
        int r = idx / KP, k = idx % KP;
        int d = r >> 2, g = r & 3;
        float v = 0.f;
        if (g == 0) {
            if (k < 304)      v = W_ih[d * 304 + k];
            else if (k < 404) v = W_hh[d * 100 + (k - 304)];
        } else if (g == 1) {
            int rr = 100 + d;
            if (k < 304)      v = W_ih[rr * 304 + k];
            else if (k < 404) v = W_hh[rr * 100 + (k - 304)];
        } else if (g == 2) {
            if (k < 304)      v = W_ih[(200 + d) * 304 + k];
        } else {
            if (k >= 304 && k < 404) v = W_hh[(200 + d) * 100 + (k - 304)];
        }
        __nv_bfloat16 hi = __float2bfloat16(v);
        g_Whi[idx] = hi;
        g_Wlo[idx] = __float2bfloat16(v - __bfloat162float(hi));
    }
    if (idx < NP) {
        int d = idx >> 2, g = idx & 3;
        float bv;
        if (g == 0)      bv = b_ih[d] + b_hh[d];
        else if (g == 1) bv = b_ih[100 + d] + b_hh[100 + d];
        else if (g == 2) bv = b_ih[200 + d];
        else             bv = b_hh[200 + d];
        g_bq[idx] = bv;
    }
    if (idx < 128) g_stats[idx] = 0.f;
}

// ===================== K1: gather + assemble X (bf16 hi/lo) =====================
__global__ __launch_bounds__(256) void assemble_kernel(const int*   __restrict__ n_id,
                                                       const float* __restrict__ memory,
                                                       const int*   __restrict__ last_update,
                                                       const int*   __restrict__ store_src,
                                                       const int*   __restrict__ store_dst,
                                                       const int*   __restrict__ store_t,
                                                       const float* __restrict__ store_msg,
                                                       const float* __restrict__ time_w,
                                                       const float* __restrict__ time_b) {
    int w = threadIdx.x >> 5, lane = threadIdx.x & 31;
    int b = blockIdx.x * 8 + w;
    int n   = n_id[b];
    int src = store_src[n];
    int dst = store_dst[n];
    float dt = (float)(store_t[n] - last_update[n]);
    const float* ms = memory + (size_t)src * DD;
    const float* md = memory + (size_t)dst * DD;
    const float* mn = memory + (size_t)n   * DD;
    __nv_bfloat16* xh = g_Xhi + (size_t)b * KP;
    __nv_bfloat16* xl = g_Xlo + (size_t)b * KP;
    #pragma unroll
    for (int c = lane; c < KP; c += 32) {
        float v;
        if (c < 100)      v = ms[c];
        else if (c < 200) v = md[c - 100];
        else if (c < 204) v = store_msg[(size_t)n * 4 + (c - 200)];
        else if (c < 304) {
            int j = c - 204;
            float arg = __fadd_rn(__fmul_rn(dt, time_w[j]), time_b[j]);  // no fma (match jax)
            v = cosf(arg);
        }
        else if (c < 404) v = mn[c - 304];
        else              v = 0.f;
        __nv_bfloat16 hi = __float2bfloat16(v);
        xh[c] = hi;
        xl[c] = __float2bfloat16(v - __bfloat162float(hi));
    }
}

// ===================== K2: HMMA GEMM (3-term bf16 split) + fused GRU epilogue ==
__global__ __launch_bounds__(256) void gemm_kernel() {
    extern __shared__ char sm[];
    const uint32_t sb = smem_u32(sm);
    const int tid = threadIdx.x, wid = tid >> 5, lane = tid & 31;
    const int m0 = blockIdx.x * BMM;
    const int nt = blockIdx.y;
    const int n0 = nt * BNN;
    const int wm0 = (wid & 3) * 32;       // warp M offset in tile
    const int wn0 = (wid >> 2) * 40;      // warp N offset in tile

    if (tid < BNN) ((float*)(sm + SBIAS))[tid] = g_bq[n0 + tid];

    float c[2][5][4];
    #pragma unroll
    for (int i = 0; i < 2; i++)
        #pragma unroll
        for (int j = 0; j < 5; j++)
            #pragma unroll
            for (int q = 0; q < 4; q++) c[i][j][q] = 0.f;

    for (int ch = 0; ch < NCHUNK; ch++) {
        __syncthreads();   // prev mma done (and bias write on first iter)
        // cooperative stage: A hi/lo (2048 x 16B) + B hi/lo (1280 x 16B)
        for (int i = tid; i < 3328; i += 256) {
            const char* src;
            char* dst;
            if (i < 2048) {
                int mat = i >> 10, r = (i >> 3) & 127, j = i & 7;
                src = (const char*)(mat ? g_Xlo : g_Xhi) + (size_t)(m0 + r) * (KP * 2) + ch * 128 + j * 16;
                dst = sm + (mat ? SA_LO : SA_HI) + r * 128 + ((j ^ (r & 7)) << 4);
            } else {
                int ii = i - 2048;
                int mat = ii >= 640, iii = ii - mat * 640;
                int r = iii >> 3, j = iii & 7;
                src = (const char*)(mat ? g_Wlo : g_Whi) + (size_t)(n0 + r) * (KP * 2) + ch * 128 + j * 16;
                dst = sm + (mat ? SB_LO : SB_HI) + r * 128 + ((j ^ (r & 7)) << 4);
            }
            *(uint4*)dst = *(const uint4*)src;
        }
        __syncthreads();
        #pragma unroll
        for (int ks = 0; ks < 4; ks++) {
            uint32_t ah[2][4], al[2][4], bh[5][2], bl[5][2];
            int arow = wm0 + (lane & 7) + ((lane >> 3) & 1) * 8;
            int achk = 2 * ks + (lane >> 4);
            #pragma unroll
            for (int i = 0; i < 2; i++) {
                int r = arow + i * 16;
                uint32_t off = r * 128 + ((achk ^ (r & 7)) << 4);
                LDSM4(ah[i], sb + SA_HI + off);
                LDSM4(al[i], sb + SA_LO + off);
            }
            int brow = wn0 + (lane & 7);
            int bchk = 2 * ks + ((lane >> 3) & 1);
            #pragma unroll
            for (int j = 0; j < 5; j++) {
                int r = brow + j * 8;
                uint32_t off = r * 128 + ((bchk ^ (r & 7)) << 4);
                LDSM2(bh[j], sb + SB_HI + off);
                LDSM2(bl[j], sb + SB_LO + off);
            }
            #pragma unroll
            for (int i = 0; i < 2; i++)
                #pragma unroll
                for (int j = 0; j < 5; j++) {
                    MMA(c[i][j], ah[i], bh[j]);
                    MMA(c[i][j], ah[i], bl[j]);
                    MMA(c[i][j], al[i], bh[j]);
                }
        }
    }
    __syncthreads();

    // stage C (+bias) into smem: 128 x 84 floats
    float* Cs = (float*)sm;
    const float* sbias = (const float*)(sm + SBIAS);
    #pragma unroll
    for (int i = 0; i < 2; i++) {
        int r0 = wm0 + i * 16 + (lane >> 2);
        #pragma unroll
        for (int j = 0; j < 5; j++) {
            int cc = wn0 + j * 8 + 2 * (lane & 3);
            float bz0 = sbias[cc], bz1 = sbias[cc + 1];
            Cs[r0 * 84 + cc]           = c[i][j][0] + bz0;
            Cs[r0 * 84 + cc + 1]       = c[i][j][1] + bz1;
            Cs[(r0 + 8) * 84 + cc]     = c[i][j][2] + bz0;
            Cs[(r0 + 8) * 84 + cc + 1] = c[i][j][3] + bz1;
        }
    }
    __syncthreads();

    // fused GRU epilogue: 128 rows x 20 quadruples
    for (int g = tid; g < 128 * 20; g += 256) {
        int m = g / 20, dl = g % 20;
        float4 v = *(const float4*)&Cs[m * 84 + 4 * dl];
        int dg = nt * 20 + dl;
        int mg = m0 + m;
        float h = __bfloat162float(g_Xhi[(size_t)mg * KP + 304 + dg]) +
                  __bfloat162float(g_Xlo[(size_t)mg * KP + 304 + dg]);
        float rr = 1.f / (1.f + __expf(-v.x));
        float zz = 1.f / (1.f + __expf(-v.y));
        float nn = tanhf(v.z + rr * v.w);
        g_HN[(size_t)mg * DD + dg] = (1.f - zz) * nn + zz * h;
    }
}

// ===================== K3: A = relu(h_new @ W1^T + b1) + BN stats =====================
__global__ __launch_bounds__(256) void w1bn_kernel(const float* __restrict__ W1,
                                                   const float* __restrict__ b1) {
    __shared__ float W1s[64 * 100];
    __shared__ __align__(16) float hns[8][100];
    __shared__ float sacc[64], qacc[64];
    int tid = threadIdx.x;
    for (int i = tid; i < 6400; i += 256) W1s[i] = W1[i];
    if (tid < 64)       sacc[tid] = 0.f;
    else if (tid < 128) qacc[tid - 64] = 0.f;
    __syncthreads();

    int w = tid >> 5, lane = tid & 31;
    float b1a = b1[lane], b1b = b1[lane + 32];
    float s0 = 0.f, q0 = 0.f, s1 = 0.f, q1 = 0.f;

    for (int t = 0; t < 8; t++) {
        int b = blockIdx.x * 64 + w * 8 + t;
        if (lane < 25)
            ((float4*)hns[w])[lane] = ((const float4*)(g_HN + (size_t)b * DD))[lane];
        __syncwarp();
        float y0 = b1a, y1 = b1b;
        const float4* hv  = (const float4*)hns[w];
        const float4* wv0 = (const float4*)(W1s + lane * 100);
        const float4* wv1 = (const float4*)(W1s + (lane + 32) * 100);
        #pragma unroll
        for (int q = 0; q < 25; q++) {
            float4 h = hv[q], a = wv0[q], cc = wv1[q];
            y0 += h.x * a.x + h.y * a.y + h.z * a.z + h.w * a.w;
            y1 += h.x * cc.x + h.y * cc.y + h.z * cc.z + h.w * cc.w;
        }
        float a0 = fmaxf(y0, 0.f), a1 = fmaxf(y1, 0.f);
        g_A[(size_t)b * 64 + lane]      = a0;
        g_A[(size_t)b * 64 + lane + 32] = a1;
        s0 += a0; q0 += a0 * a0;
        s1 += a1; q1 += a1 * a1;
        __syncwarp();
    }
    atomicAdd(&sacc[lane],      s0); atomicAdd(&qacc[lane],      q0);
    atomicAdd(&sacc[lane + 32], s1); atomicAdd(&qacc[lane + 32], q1);
    __syncthreads();
    if (tid < 64) {
        atomicAdd(&g_stats[tid],      sacc[tid]);
        atomicAdd(&g_stats[64 + tid], qacc[tid]);
    }
}

// ===================== K4: finalize BN, fold into W2 =====================
__global__ void finalize_kernel(const float* __restrict__ gamma,
                                const float* __restrict__ beta,
                                const float* __restrict__ W2,
                                const float* __restrict__ b2) {
    __shared__ float red0[64], red1[64];
    int j = threadIdx.x;
    float mu  = g_stats[j]      * (1.f / BATCH);
    float var = g_stats[64 + j] * (1.f / BATCH) - mu * mu;
    float inv = rsqrtf(var + 1e-5f);
    float gsc = gamma[j] * inv;
    float w0 = W2[j], w1 = W2[64 + j];
    g_W2e[2 * j]     = w0 * gsc;
    g_W2e[2 * j + 1] = w1 * gsc;
    float c = beta[j] - mu * gsc;
    red0[j] = c * w0;
    red1[j] = c * w1;
    __syncthreads();
    if (j == 0) { float s = 0.f; for (int i = 0; i < 64; i++) s += red0[i]; g_be[0] = b2[0] + s; }
    if (j == 1) { float s = 0.f; for (int i = 0; i < 64; i++) s += red1[i]; g_be[1] = b2[1] + s; }
}

// ===================== K5: output = A @ W2e + be =====================
__global__ __launch_bounds__(256) void out_kernel(float* __restrict__ out) {
    __shared__ float w2s[128];
    __shared__ float bes[2];
    int tid = threadIdx.x;
    if (tid < 128) w2s[tid] = g_W2e[tid];
    if (tid < 2)   bes[tid] = g_be[tid];
    __syncthreads();
    int b = blockIdx.x * 256 + tid;
    const float4* ar = (const float4*)(g_A + (size_t)b * 64);
    float o0 = bes[0], o1 = bes[1];
    #pragma unroll
    for (int q = 0; q < 16; q++) {
        float4 v = ar[q];
        int j = q * 8;
        o0 += v.x * w2s[j]     + v.y * w2s[j + 2] + v.z * w2s[j + 4] + v.w * w2s[j + 6];
        o1 += v.x * w2s[j + 1] + v.y * w2s[j + 3] + v.z * w2s[j + 5] + v.w * w2s[j + 7];
    }
    ((float2*)out)[b] = make_float2(o0, o1);
}

// ===================== launcher =====================
extern "C" void kernel_launch(void* const* d_in, const int* in_sizes, int n_in,
                              void* d_out, int out_size) {
    const int*   n_id        = (const int*)  d_in[0];
    const float* memory      = (const float*)d_in[1];
    const int*   last_update = (const int*)  d_in[2];
    const int*   store_src   = (const int*)  d_in[3];
    const int*   store_dst   = (const int*)  d_in[4];
    const int*   store_t     = (const int*)  d_in[5];
    const float* store_msg   = (const float*)d_in[6];
    const float* time_w      = (const float*)d_in[7];
    const float* time_b      = (const float*)d_in[8];
    const float* W_ih        = (const float*)d_in[9];
    const float* b_ih        = (const float*)d_in[10];
    const float* W_hh        = (const float*)d_in[11];
    const float* b_hh        = (const float*)d_in[12];
    const float* W1          = (const float*)d_in[13];
    const float* b1          = (const float*)d_in[14];
    const float* gamma       = (const float*)d_in[15];
    const float* beta        = (const float*)d_in[16];
    const float* W2          = (const float*)d_in[17];
    const float* b2          = (const float*)d_in[18];
    float*       out         = (float*)d_out;

    static int smem_set = 0;
    if (!smem_set) {
        cudaFuncSetAttribute(gemm_kernel, cudaFuncAttributeMaxDynamicSharedMemorySize, SMEM_TOT);
        smem_set = 1;
    }

    prep_kernel<<<(NP * KP + 255) / 256, 256>>>(W_ih, W_hh, b_ih, b_hh);
    assemble_kernel<<<BATCH / 8, 256>>>(n_id, memory, last_update, store_src,
                                        store_dst, store_t, store_msg, time_w, time_b);
    gemm_kernel<<<dim3(BATCH / BMM, 5), 256, SMEM_TOT>>>();
    w1bn_kernel<<<BATCH / 64, 256>>>(W1, b1);
    finalize_kernel<<<1, 64>>>(gamma, beta, W2, b2);
    out_kernel<<<BATCH / 256, 256>>>(out);
}

// round 5
// speedup vs baseline: 2.3916x; 1.9929x over previous
#include <cuda_runtime.h>
#include <cuda_bf16.h>
#include <math.h>
#include <stdint.h>

#define BATCH   262144
#define DD      100
#define KP      448       // padded K (bf16 cols): 404 -> 448
#define NP      400       // interleaved gate rows: 100 quadruples (r,z,n,hn)
#define BMM     128
#define BNN     80
#define NCHUNK  7         // 448/64

// -------- device scratch --------
__device__ __nv_bfloat16 g_Xhi[(size_t)BATCH * KP];
__device__ __nv_bfloat16 g_Xlo[(size_t)BATCH * KP];
__device__ __nv_bfloat16 g_Whi[(size_t)NP * KP];
__device__ __nv_bfloat16 g_Wlo[(size_t)NP * KP];
__device__ float g_bq[NP];
__device__ float g_HN[(size_t)BATCH * DD];     // h_new fp32
__device__ float g_A [(size_t)BATCH * 64];
__device__ float g_stats[128];
__device__ float g_W2e[128];
__device__ float g_be[2];

__device__ __forceinline__ uint32_t smem_u32(const void* p) {
    uint32_t a;
    asm("{ .reg .u64 t; cvta.to.shared.u64 t, %1; cvt.u32.u64 %0, t; }" : "=r"(a) : "l"(p));
    return a;
}
#define LDSM4(r, a) asm volatile("ldmatrix.sync.aligned.m8n8.x4.shared.b16 {%0,%1,%2,%3}, [%4];" \
    : "=r"((r)[0]), "=r"((r)[1]), "=r"((r)[2]), "=r"((r)[3]) : "r"(a))
#define LDSM2(r, a) asm volatile("ldmatrix.sync.aligned.m8n8.x2.shared.b16 {%0,%1}, [%2];" \
    : "=r"((r)[0]), "=r"((r)[1]) : "r"(a))
#define MMA(c, a, b) asm volatile( \
    "mma.sync.aligned.m16n8k16.row.col.f32.bf16.bf16.f32 {%0,%1,%2,%3},{%4,%5,%6,%7},{%8,%9},{%0,%1,%2,%3};" \
    : "+f"((c)[0]), "+f"((c)[1]), "+f"((c)[2]), "+f"((c)[3])                                                  \
    : "r"((a)[0]), "r"((a)[1]), "r"((a)[2]), "r"((a)[3]), "r"((b)[0]), "r"((b)[1]))
__device__ __forceinline__ void cpa16(uint32_t d, const void* s) {
    asm volatile("{ .reg .u64 g; cvta.to.global.u64 g, %1; cp.async.cg.shared.global [%0], [g], 16; }"
                 :: "r"(d), "l"(s));
}
#define CPA_COMMIT() asm volatile("cp.async.commit_group;" ::: "memory")

// smem layout: two 52KB stages, then bias
// stage s base = s * 53248 ; within stage: A_HI 0, A_LO 16384, B_HI 32768, B_LO 43008
#define STAGE_SZ 53248
#define SBIAS    106496
#define SMEM_TOT 106880
// C staging (128 x 84 floats = 43008 B) reuses stage 0

// ===================== K0: prep interleaved split weights =====================
__global__ __launch_bounds__(256) void prep_kernel(const float* __restrict__ W_ih,
                                                   const float* __restrict__ W_hh,
                                                   const float* __restrict__ b_ih,
                                                   const float* __restrict__ b_hh) {
    int idx = blockIdx.x * 256 + threadIdx.x;
    if (idx < NP * KP) {
        int r = idx / KP, k = idx % KP;
        int d = r >> 2, g = r & 3;
        float v = 0.f;
        if (g == 0) {
            if (k < 304)      v = W_ih[d * 304 + k];
            else if (k < 404) v = W_hh[d * 100 + (k - 304)];
        } else if (g == 1) {
            int rr = 100 + d;
            if (k < 304)      v = W_ih[rr * 304 + k];
            else if (k < 404) v = W_hh[rr * 100 + (k - 304)];
        } else if (g == 2) {
            if (k < 304)      v = W_ih[(200 + d) * 304 + k];
        } else {
            if (k >= 304 && k < 404) v = W_hh[(200 + d) * 100 + (k - 304)];
        }
        __nv_bfloat16 hi = __float2bfloat16(v);
        g_Whi[idx] = hi;
        g_Wlo[idx] = __float2bfloat16(v - __bfloat162float(hi));
    }
    if (idx < NP) {
        int d = idx >> 2, g = idx & 3;
        float bv;
        if (g == 0)      bv = b_ih[d] + b_hh[d];
        else if (g == 1) bv = b_ih[100 + d] + b_hh[100 + d];
        else if (g == 2) bv = b_ih[200 + d];
        else             bv = b_hh[200 + d];
        g_bq[idx] = bv;
    }
    if (idx < 128) g_stats[idx] = 0.f;
}

// ===================== K1: gather + assemble X (bf16 hi/lo) =====================
__global__ __launch_bounds__(256) void assemble_kernel(const int*   __restrict__ n_id,
                                                       const float* __restrict__ memory,
                                                       const int*   __restrict__ last_update,
                                                       const int*   __restrict__ store_src,
                                                       const int*   __restrict__ store_dst,
                                                       const int*   __restrict__ store_t,
                                                       const float* __restrict__ store_msg,
                                                       const float* __restrict__ time_w,
                                                       const float* __restrict__ time_b) {
    int w = threadIdx.x >> 5, lane = threadIdx.x & 31;
    int b = blockIdx.x * 8 + w;
    int n   = n_id[b];
    int src = store_src[n];
    int dst = store_dst[n];
    float dt = (float)(store_t[n] - last_update[n]);
    const float* ms = memory + (size_t)src * DD;
    const float* md = memory + (size_t)dst * DD;
    const float* mn = memory + (size_t)n   * DD;
    __nv_bfloat16* xh = g_Xhi + (size_t)b * KP;
    __nv_bfloat16* xl = g_Xlo + (size_t)b * KP;
    #pragma unroll
    for (int c = lane; c < KP; c += 32) {
        float v;
        if (c < 100)      v = ms[c];
        else if (c < 200) v = md[c - 100];
        else if (c < 204) v = store_msg[(size_t)n * 4 + (c - 200)];
        else if (c < 304) {
            int j = c - 204;
            float arg = __fadd_rn(__fmul_rn(dt, time_w[j]), time_b[j]);  // no fma (match jax)
            v = cosf(arg);
        }
        else if (c < 404) v = mn[c - 304];
        else              v = 0.f;
        __nv_bfloat16 hi = __float2bfloat16(v);
        xh[c] = hi;
        xl[c] = __float2bfloat16(v - __bfloat162float(hi));
    }
}

// ===================== K2: HMMA GEMM (3-term bf16 split, cp.async pipeline) ====
__global__ __launch_bounds__(256, 2) void gemm_kernel() {
    extern __shared__ char sm[];
    const uint32_t sb = smem_u32(sm);
    const int tid = threadIdx.x, wid = tid >> 5, lane = tid & 31;
    const int m0 = blockIdx.x * BMM;
    const int nt = blockIdx.y;
    const int n0 = nt * BNN;
    const int wm0 = (wid & 3) * 32;       // warp M offset
    const int wn0 = (wid >> 2) * 40;      // warp N offset

    if (tid < BNN) ((float*)(sm + SBIAS))[tid] = g_bq[n0 + tid];

    float c[2][5][4];
    #pragma unroll
    for (int i = 0; i < 2; i++)
        #pragma unroll
        for (int j = 0; j < 5; j++)
            #pragma unroll
            for (int q = 0; q < 4; q++) c[i][j][q] = 0.f;

    // -------- staging lambda (13 x 16B cp.async per thread) --------
    auto stage = [&](int ch, uint32_t base) {
        #pragma unroll 1
        for (int i = tid; i < 3328; i += 256) {
            uint32_t dst;
            const char* src;
            if (i < 2048) {
                int mat = i >> 10, r = (i >> 3) & 127, j = i & 7;
                src = (const char*)(mat ? g_Xlo : g_Xhi) + (size_t)(m0 + r) * (KP * 2) + ch * 128 + j * 16;
                dst = base + (mat ? 16384 : 0) + r * 128 + ((j ^ (r & 7)) << 4);
            } else {
                int ii = i - 2048;
                int mat = ii >= 640, iii = ii - mat * 640;
                int r = iii >> 3, j = iii & 7;
                src = (const char*)(mat ? g_Wlo : g_Whi) + (size_t)(n0 + r) * (KP * 2) + ch * 128 + j * 16;
                dst = base + 32768 + (mat ? 10240 : 0) + r * 128 + ((j ^ (r & 7)) << 4);
            }
            cpa16(dst, src);
        }
        CPA_COMMIT();
    };

    stage(0, sb);   // prefetch chunk 0 -> stage 0

    for (int ch = 0; ch < NCHUNK; ch++) {
        if (ch < NCHUNK - 1) {
            stage(ch + 1, sb + ((ch + 1) & 1) * STAGE_SZ);
            asm volatile("cp.async.wait_group 1;" ::: "memory");
        } else {
            asm volatile("cp.async.wait_group 0;" ::: "memory");
        }
        __syncthreads();
        const uint32_t st = sb + (ch & 1) * STAGE_SZ;
        #pragma unroll
        for (int ks = 0; ks < 4; ks++) {
            uint32_t ah[2][4], al[2][4], bh[5][2], bl[5][2];
            int arow = wm0 + (lane & 7) + ((lane >> 3) & 1) * 8;
            int achk = 2 * ks + (lane >> 4);
            #pragma unroll
            for (int i = 0; i < 2; i++) {
                int r = arow + i * 16;
                uint32_t off = r * 128 + ((achk ^ (r & 7)) << 4);
                LDSM4(ah[i], st + off);
                LDSM4(al[i], st + 16384 + off);
            }
            int brow = wn0 + (lane & 7);
            int bchk = 2 * ks + ((lane >> 3) & 1);
            #pragma unroll
            for (int j = 0; j < 5; j++) {
                int r = brow + j * 8;
                uint32_t off = r * 128 + ((bchk ^ (r & 7)) << 4);
                LDSM2(bh[j], st + 32768 + off);
                LDSM2(bl[j], st + 43008 + off);
            }
            #pragma unroll
            for (int i = 0; i < 2; i++)
                #pragma unroll
                for (int j = 0; j < 5; j++) {
                    MMA(c[i][j], ah[i], bh[j]);
                    MMA(c[i][j], ah[i], bl[j]);
                    MMA(c[i][j], al[i], bh[j]);
                }
        }
        __syncthreads();   // mma done before buffer (ch&1) is overwritten at ch+1's stage()
    }

    // stage C (+bias) into smem: 128 x 84 floats (reuses stage 0)
    float* Cs = (float*)sm;
    const float* sbias = (const float*)(sm + SBIAS);
    #pragma unroll
    for (int i = 0; i < 2; i++) {
        int r0 = wm0 + i * 16 + (lane >> 2);
        #pragma unroll
        for (int j = 0; j < 5; j++) {
            int cc = wn0 + j * 8 + 2 * (lane & 3);
            float bz0 = sbias[cc], bz1 = sbias[cc + 1];
            Cs[r0 * 84 + cc]           = c[i][j][0] + bz0;
            Cs[r0 * 84 + cc + 1]       = c[i][j][1] + bz1;
            Cs[(r0 + 8) * 84 + cc]     = c[i][j][2] + bz0;
            Cs[(r0 + 8) * 84 + cc + 1] = c[i][j][3] + bz1;
        }
    }
    __syncthreads();

    // fused GRU epilogue: 128 rows x 20 quadruples
    for (int g = tid; g < 128 * 20; g += 256) {
        int m = g / 20, dl = g % 20;
        float4 v = *(const float4*)&Cs[m * 84 + 4 * dl];
        int dg = nt * 20 + dl;
        int mg = m0 + m;
        float h = __bfloat162float(g_Xhi[(size_t)mg * KP + 304 + dg]) +
                  __bfloat162float(g_Xlo[(size_t)mg * KP + 304 + dg]);
        float rr = 1.f / (1.f + __expf(-v.x));
        float zz = 1.f / (1.f + __expf(-v.y));
        float nn = tanhf(v.z + rr * v.w);
        g_HN[(size_t)mg * DD + dg] = (1.f - zz) * nn + zz * h;
    }
}

// ===================== K3: A = relu(h_new @ W1^T + b1) + BN stats =====================
// 8 warps; each warp 8 rows in two groups of 4; weight loads amortized over 4 rows
__global__ __launch_bounds__(256) void w1bn_kernel(const float* __restrict__ W1,
                                                   const float* __restrict__ b1) {
    __shared__ float W1s[64 * 100];
    __shared__ __align__(16) float hns[8][4][100];
    __shared__ float sacc[64], qacc[64];
    int tid = threadIdx.x;
    for (int i = tid; i < 6400; i += 256) W1s[i] = W1[i];
    if (tid < 64)       sacc[tid] = 0.f;
    else if (tid < 128) qacc[tid - 64] = 0.f;
    __syncthreads();

    int w = tid >> 5, lane = tid & 31;
    float b1a = b1[lane], b1b = b1[lane + 32];
    float s0 = 0.f, q0 = 0.f, s1 = 0.f, q1 = 0.f;
    const float4* wv0 = (const float4*)(W1s + lane * 100);
    const float4* wv1 = (const float4*)(W1s + (lane + 32) * 100);

    #pragma unroll
    for (int t4 = 0; t4 < 8; t4 += 4) {
        int b0 = blockIdx.x * 64 + w * 8 + t4;
        // rows b0..b0+3 are contiguous: 400 floats = 100 float4
        for (int i = lane; i < 100; i += 32)
            ((float4*)hns[w])[i] = ((const float4*)(g_HN + (size_t)b0 * DD))[i];
        __syncwarp();
        float y[4][2];
        #pragma unroll
        for (int r = 0; r < 4; r++) { y[r][0] = b1a; y[r][1] = b1b; }
        #pragma unroll
        for (int q = 0; q < 25; q++) {
            float4 a = wv0[q], cw = wv1[q];
            #pragma unroll
            for (int r = 0; r < 4; r++) {
                float4 h = ((const float4*)hns[w][r])[q];
                y[r][0] += h.x * a.x + h.y * a.y + h.z * a.z + h.w * a.w;
                y[r][1] += h.x * cw.x + h.y * cw.y + h.z * cw.z + h.w * cw.w;
            }
        }
        #pragma unroll
        for (int r = 0; r < 4; r++) {
            float a0 = fmaxf(y[r][0], 0.f), a1 = fmaxf(y[r][1], 0.f);
            g_A[(size_t)(b0 + r) * 64 + lane]      = a0;
            g_A[(size_t)(b0 + r) * 64 + lane + 32] = a1;
            s0 += a0; q0 += a0 * a0;
            s1 += a1; q1 += a1 * a1;
        }
        __syncwarp();
    }
    atomicAdd(&sacc[lane],      s0); atomicAdd(&qacc[lane],      q0);
    atomicAdd(&sacc[lane + 32], s1); atomicAdd(&qacc[lane + 32], q1);
    __syncthreads();
    if (tid < 64) {
        atomicAdd(&g_stats[tid],      sacc[tid]);
        atomicAdd(&g_stats[64 + tid], qacc[tid]);
    }
}

// ===================== K4: finalize BN, fold into W2 =====================
__global__ void finalize_kernel(const float* __restrict__ gamma,
                                const float* __restrict__ beta,
                                const float* __restrict__ W2,
                                const float* __restrict__ b2) {
    __shared__ float red0[64], red1[64];
    int j = threadIdx.x;
    float mu  = g_stats[j]      * (1.f / BATCH);
    float var = g_stats[64 + j] * (1.f / BATCH) - mu * mu;
    float inv = rsqrtf(var + 1e-5f);
    float gsc = gamma[j] * inv;
    float w0 = W2[j], w1 = W2[64 + j];
    g_W2e[2 * j]     = w0 * gsc;
    g_W2e[2 * j + 1] = w1 * gsc;
    float c = beta[j] - mu * gsc;
    red0[j] = c * w0;
    red1[j] = c * w1;
    __syncthreads();
    if (j == 0) { float s = 0.f; for (int i = 0; i < 64; i++) s += red0[i]; g_be[0] = b2[0] + s; }
    if (j == 1) { float s = 0.f; for (int i = 0; i < 64; i++) s += red1[i]; g_be[1] = b2[1] + s; }
}

// ===================== K5: output = A @ W2e + be =====================
__global__ __launch_bounds__(256) void out_kernel(float* __restrict__ out) {
    __shared__ float w2s[128];
    __shared__ float bes[2];
    int tid = threadIdx.x;
    if (tid < 128) w2s[tid] = g_W2e[tid];
    if (tid < 2)   bes[tid] = g_be[tid];
    __syncthreads();
    int b = blockIdx.x * 256 + tid;
    const float4* ar = (const float4*)(g_A + (size_t)b * 64);
    float o0 = bes[0], o1 = bes[1];
    #pragma unroll
    for (int q = 0; q < 16; q++) {
        float4 v = ar[q];
        int j = q * 8;
        o0 += v.x * w2s[j]     + v.y * w2s[j + 2] + v.z * w2s[j + 4] + v.w * w2s[j + 6];
        o1 += v.x * w2s[j + 1] + v.y * w2s[j + 3] + v.z * w2s[j + 5] + v.w * w2s[j + 7];
    }
    ((float2*)out)[b] = make_float2(o0, o1);
}

// ===================== launcher =====================
extern "C" void kernel_launch(void* const* d_in, const int* in_sizes, int n_in,
                              void* d_out, int out_size) {
    const int*   n_id        = (const int*)  d_in[0];
    const float* memory      = (const float*)d_in[1];
    const int*   last_update = (const int*)  d_in[2];
    const int*   store_src   = (const int*)  d_in[3];
    const int*   store_dst   = (const int*)  d_in[4];
    const int*   store_t     = (const int*)  d_in[5];
    const float* store_msg   = (const float*)d_in[6];
    const float* time_w      = (const float*)d_in[7];
    const float* time_b      = (const float*)d_in[8];
    const float* W_ih        = (const float*)d_in[9];
    const float* b_ih        = (const float*)d_in[10];
    const float* W_hh        = (const float*)d_in[11];
    const float* b_hh        = (const float*)d_in[12];
    const float* W1          = (const float*)d_in[13];
    const float* b1          = (const float*)d_in[14];
    const float* gamma       = (const float*)d_in[15];
    const float* beta        = (const float*)d_in[16];
    const float* W2          = (const float*)d_in[17];
    const float* b2          = (const float*)d_in[18];
    float*       out         = (float*)d_out;

    cudaFuncSetAttribute(gemm_kernel, cudaFuncAttributeMaxDynamicSharedMemorySize, SMEM_TOT);

    prep_kernel<<<(NP * KP + 255) / 256, 256>>>(W_ih, W_hh, b_ih, b_hh);
    assemble_kernel<<<BATCH / 8, 256>>>(n_id, memory, last_update, store_src,
                                        store_dst, store_t, store_msg, time_w, time_b);
    gemm_kernel<<<dim3(BATCH / BMM, 5), 256, SMEM_TOT>>>();
    w1bn_kernel<<<BATCH / 64, 256>>>(W1, b1);
    finalize_kernel<<<1, 64>>>(gamma, beta, W2, b2);
    out_kernel<<<BATCH / 256, 256>>>(out);
}

// round 7
// speedup vs baseline: 2.8528x; 1.1928x over previous
#include <cuda_runtime.h>
#include <cuda_fp16.h>
#include <math.h>
#include <stdint.h>

#define BATCH   262144
#define DD      100
#define KP      448       // padded K (fp16 cols): 404 -> 448
#define NP      400       // interleaved gate rows: 100 quadruples (r,z,n,hn)
#define BMM     128
#define BNN     80
#define NCHUNK  7         // 448/64

// -------- device scratch --------
__device__ __half g_Xhi[(size_t)BATCH * KP];
__device__ __half g_Xlo[(size_t)BATCH * KP];   // only for exact-h reconstruction
__device__ __half g_Whi[(size_t)NP * KP];
__device__ __half g_Wlo[(size_t)NP * KP];
__device__ float g_bq[NP];
__device__ float g_HN[(size_t)BATCH * DD];     // h_new fp32
__device__ float g_A [(size_t)BATCH * 64];
__device__ float g_stats[128];
__device__ float g_W2e[128];
__device__ float g_be[2];

__device__ __forceinline__ uint32_t smem_u32(const void* p) {
    uint32_t a;
    asm("{ .reg .u64 t; cvta.to.shared.u64 t, %1; cvt.u32.u64 %0, t; }" : "=r"(a) : "l"(p));
    return a;
}
#define LDSM4(r, a) asm volatile("ldmatrix.sync.aligned.m8n8.x4.shared.b16 {%0,%1,%2,%3}, [%4];" \
    : "=r"((r)[0]), "=r"((r)[1]), "=r"((r)[2]), "=r"((r)[3]) : "r"(a))
#define LDSM2(r, a) asm volatile("ldmatrix.sync.aligned.m8n8.x2.shared.b16 {%0,%1}, [%2];" \
    : "=r"((r)[0]), "=r"((r)[1]) : "r"(a))
#define MMA(c, a, b) asm volatile( \
    "mma.sync.aligned.m16n8k16.row.col.f32.f16.f16.f32 {%0,%1,%2,%3},{%4,%5,%6,%7},{%8,%9},{%0,%1,%2,%3};" \
    : "+f"((c)[0]), "+f"((c)[1]), "+f"((c)[2]), "+f"((c)[3])                                                \
    : "r"((a)[0]), "r"((a)[1]), "r"((a)[2]), "r"((a)[3]), "r"((b)[0]), "r"((b)[1]))
__device__ __forceinline__ void cpa16(uint32_t d, const void* s) {
    asm volatile("{ .reg .u64 g; cvta.to.global.u64 g, %1; cp.async.cg.shared.global [%0], [g], 16; }"
                 :: "r"(d), "l"(s));
}
#define CPA_COMMIT() asm volatile("cp.async.commit_group;" ::: "memory")

// smem stage: A_HI [0,16384), B_HI [16384,26624), B_LO [26624,36864)
#define STAGE_SZ 36864
#define SBIAS    73728
#define SMEM_TOT 74112
// C staging (128 x 84 floats = 43008 B) reuses stages

// ===================== K0: prep interleaved split weights =====================
__global__ __launch_bounds__(256) void prep_kernel(const float* __restrict__ W_ih,
                                                   const float* __restrict__ W_hh,
                                                   const float* __restrict__ b_ih,
                                                   const float* __restrict__ b_hh) {
    int idx = blockIdx.x * 256 + threadIdx.x;
    if (idx < NP * KP) {
        int r = idx / KP, k = idx % KP;
        int d = r >> 2, g = r & 3;
        float v = 0.f;
        if (g == 0) {
            if (k < 304)      v = W_ih[d * 304 + k];
            else if (k < 404) v = W_hh[d * 100 + (k - 304)];
        } else if (g == 1) {
            int rr = 100 + d;
            if (k < 304)      v = W_ih[rr * 304 + k];
            else if (k < 404) v = W_hh[rr * 100 + (k - 304)];
        } else if (g == 2) {
            if (k < 304)      v = W_ih[(200 + d) * 304 + k];
        } else {
            if (k >= 304 && k < 404) v = W_hh[(200 + d) * 100 + (k - 304)];
        }
        __half hi = __float2half(v);
        g_Whi[idx] = hi;
        g_Wlo[idx] = __float2half(v - __half2float(hi));
    }
    if (idx < NP) {
        int d = idx >> 2, g = idx & 3;
        float bv;
        if (g == 0)      bv = b_ih[d] + b_hh[d];
        else if (g == 1) bv = b_ih[100 + d] + b_hh[100 + d];
        else if (g == 2) bv = b_ih[200 + d];
        else             bv = b_hh[200 + d];
        g_bq[idx] = bv;
    }
    if (idx < 128) g_stats[idx] = 0.f;
}

// ===================== K1: gather + assemble X (fp16 hi/lo) =====================
__global__ __launch_bounds__(256) void assemble_kernel(const int*   __restrict__ n_id,
                                                       const float* __restrict__ memory,
                                                       const int*   __restrict__ last_update,
                                                       const int*   __restrict__ store_src,
                                                       const int*   __restrict__ store_dst,
                                                       const int*   __restrict__ store_t,
                                                       const float* __restrict__ store_msg,
                                                       const float* __restrict__ time_w,
                                                       const float* __restrict__ time_b) {
    int w = threadIdx.x >> 5, lane = threadIdx.x & 31;
    int b = blockIdx.x * 8 + w;
    int n   = n_id[b];
    int src = store_src[n];
    int dst = store_dst[n];
    float dt = (float)(store_t[n] - last_update[n]);
    const float* ms = memory + (size_t)src * DD;
    const float* md = memory + (size_t)dst * DD;
    const float* mn = memory + (size_t)n   * DD;
    __half* xh = g_Xhi + (size_t)b * KP;
    __half* xl = g_Xlo + (size_t)b * KP;
    #pragma unroll
    for (int c = lane; c < KP; c += 32) {
        float v;
        if (c < 100)      v = ms[c];
        else if (c < 200) v = md[c - 100];
        else if (c < 204) v = store_msg[(size_t)n * 4 + (c - 200)];
        else if (c < 304) {
            int j = c - 204;
            float arg = __fadd_rn(__fmul_rn(dt, time_w[j]), time_b[j]);  // no fma (match jax)
            v = cosf(arg);
        }
        else if (c < 404) v = mn[c - 304];
        else              v = 0.f;
        __half hi = __float2half(v);
        xh[c] = hi;
        xl[c] = __float2half(v - __half2float(hi));
    }
}

// ===================== K2: HMMA GEMM (fp16 2-pass: Xh*Wh + Xh*Wl) ====
__global__ __launch_bounds__(256, 2) void gemm_kernel() {
    extern __shared__ char sm[];
    const uint32_t sb = smem_u32(sm);
    const int tid = threadIdx.x, wid = tid >> 5, lane = tid & 31;
    const int m0 = blockIdx.x * BMM;
    const int nt = blockIdx.y;
    const int n0 = nt * BNN;
    const int wm0 = (wid & 3) * 32;       // warp M offset
    const int wn0 = (wid >> 2) * 40;      // warp N offset

    if (tid < BNN) ((float*)(sm + SBIAS))[tid] = g_bq[n0 + tid];

    float c[2][5][4];
    #pragma unroll
    for (int i = 0; i < 2; i++)
        #pragma unroll
        for (int j = 0; j < 5; j++)
            #pragma unroll
            for (int q = 0; q < 4; q++) c[i][j][q] = 0.f;

    // -------- staging lambda (9 x 16B cp.async per thread) --------
    auto stage = [&](int ch, uint32_t base) {
        #pragma unroll 1
        for (int i = tid; i < 2304; i += 256) {
            uint32_t dst;
            const char* src;
            if (i < 1024) {
                int r = i >> 3, j = i & 7;
                src = (const char*)g_Xhi + (size_t)(m0 + r) * (KP * 2) + ch * 128 + j * 16;
                dst = base + r * 128 + ((j ^ (r & 7)) << 4);
            } else {
                int ii = i - 1024;
                int mat = ii >= 640, iii = ii - mat * 640;
                int r = iii >> 3, j = iii & 7;
                src = (const char*)(mat ? g_Wlo : g_Whi) + (size_t)(n0 + r) * (KP * 2) + ch * 128 + j * 16;
                dst = base + 16384 + (mat ? 10240 : 0) + r * 128 + ((j ^ (r & 7)) << 4);
            }
            cpa16(dst, src);
        }
        CPA_COMMIT();
    };

    stage(0, sb);   // prefetch chunk 0 -> stage 0

    for (int ch = 0; ch < NCHUNK; ch++) {
        if (ch < NCHUNK - 1) {
            stage(ch + 1, sb + ((ch + 1) & 1) * STAGE_SZ);
            asm volatile("cp.async.wait_group 1;" ::: "memory");
        } else {
            asm volatile("cp.async.wait_group 0;" ::: "memory");
        }
        __syncthreads();
        const uint32_t st = sb + (ch & 1) * STAGE_SZ;
        #pragma unroll
        for (int ks = 0; ks < 4; ks++) {
            uint32_t ah[2][4], bh[5][2], bl[5][2];
            // A hi fragments
            int arow = wm0 + (lane & 7) + ((lane >> 3) & 1) * 8;
            int achk = 2 * ks + (lane >> 4);
            #pragma unroll
            for (int i = 0; i < 2; i++) {
                int r = arow + i * 16;
                LDSM4(ah[i], st + r * 128 + ((achk ^ (r & 7)) << 4));
            }
            // B fragments: j-pairs via LDSM4 (lanes 0-7: j0/half0, 8-15: j0/half1,
            // 16-23: j0+1/half0, 24-31: j0+1/half1), tail block j=4 via LDSM2
            {
                int rr = wn0 + (lane & 7);
                int chk2 = 2 * ks + ((lane >> 3) & 1);
                #pragma unroll
                for (int jp = 0; jp < 2; jp++) {
                    int r = rr + (jp * 2 + (lane >> 4)) * 8;
                    uint32_t off = r * 128 + ((chk2 ^ (r & 7)) << 4);
                    uint32_t t4[4];
                    LDSM4(t4, st + 16384 + off);
                    bh[jp*2][0] = t4[0]; bh[jp*2][1] = t4[1];
                    bh[jp*2+1][0] = t4[2]; bh[jp*2+1][1] = t4[3];
                    LDSM4(t4, st + 26624 + off);
                    bl[jp*2][0] = t4[0]; bl[jp*2][1] = t4[1];
                    bl[jp*2+1][0] = t4[2]; bl[jp*2+1][1] = t4[3];
                }
                int r = rr + 32;
                uint32_t off = r * 128 + ((chk2 ^ (r & 7)) << 4);
                LDSM2(bh[4], st + 16384 + off);
                LDSM2(bl[4], st + 26624 + off);
            }
            #pragma unroll
            for (int i = 0; i < 2; i++)
                #pragma unroll
                for (int j = 0; j < 5; j++) {
                    MMA(c[i][j], ah[i], bh[j]);
                    MMA(c[i][j], ah[i], bl[j]);
                }
        }
        __syncthreads();   // mma done before buffer (ch&1) is overwritten
    }

    // stage C (+bias) into smem: 128 x 84 floats
    float* Cs = (float*)sm;
    const float* sbias = (const float*)(sm + SBIAS);
    #pragma unroll
    for (int i = 0; i < 2; i++) {
        int r0 = wm0 + i * 16 + (lane >> 2);
        #pragma unroll
        for (int j = 0; j < 5; j++) {
            int cc = wn0 + j * 8 + 2 * (lane & 3);
            float bz0 = sbias[cc], bz1 = sbias[cc + 1];
            Cs[r0 * 84 + cc]           = c[i][j][0] + bz0;
            Cs[r0 * 84 + cc + 1]       = c[i][j][1] + bz1;
            Cs[(r0 + 8) * 84 + cc]     = c[i][j][2] + bz0;
            Cs[(r0 + 8) * 84 + cc + 1] = c[i][j][3] + bz1;
        }
    }
    __syncthreads();

    // fused GRU epilogue: 128 rows x 20 quadruples
    for (int g = tid; g < 128 * 20; g += 256) {
        int m = g / 20, dl = g % 20;
        float4 v = *(const float4*)&Cs[m * 84 + 4 * dl];
        int dg = nt * 20 + dl;
        int mg = m0 + m;
        float h = __half2float(g_Xhi[(size_t)mg * KP + 304 + dg]) +
                  __half2float(g_Xlo[(size_t)mg * KP + 304 + dg]);
        float rr = 1.f / (1.f + __expf(-v.x));
        float zz = 1.f / (1.f + __expf(-v.y));
        float nn = tanhf(v.z + rr * v.w);
        g_HN[(size_t)mg * DD + dg] = (1.f - zz) * nn + zz * h;
    }
}

// ===================== K3: A = relu(h_new @ W1^T + b1) + BN stats =====================
__global__ __launch_bounds__(256) void w1bn_kernel(const float* __restrict__ W1,
                                                   const float* __restrict__ b1) {
    __shared__ float W1s[64 * 100];
    __shared__ __align__(16) float hns[8][4][100];
    __shared__ float sacc[64], qacc[64];
    int tid = threadIdx.x;
    for (int i = tid; i < 6400; i += 256) W1s[i] = W1[i];
    if (tid < 64)       sacc[tid] = 0.f;
    else if (tid < 128) qacc[tid - 64] = 0.f;
    __syncthreads();

    int w = tid >> 5, lane = tid & 31;
    float b1a = b1[lane], b1b = b1[lane + 32];
    float s0 = 0.f, q0 = 0.f, s1 = 0.f, q1 = 0.f;
    const float4* wv0 = (const float4*)(W1s + lane * 100);
    const float4* wv1 = (const float4*)(W1s + (lane + 32) * 100);

    #pragma unroll
    for (int t4 = 0; t4 < 8; t4 += 4) {
        int b0 = blockIdx.x * 64 + w * 8 + t4;
        for (int i = lane; i < 100; i += 32)
            ((float4*)hns[w])[i] = ((const float4*)(g_HN + (size_t)b0 * DD))[i];
        __syncwarp();
        float y[4][2];
        #pragma unroll
        for (int r = 0; r < 4; r++) { y[r][0] = b1a; y[r][1] = b1b; }
        #pragma unroll
        for (int q = 0; q < 25; q++) {
            float4 a = wv0[q], cw = wv1[q];
            #pragma unroll
            for (int r = 0; r < 4; r++) {
                float4 h = ((const float4*)hns[w][r])[q];
                y[r][0] += h.x * a.x + h.y * a.y + h.z * a.z + h.w * a.w;
                y[r][1] += h.x * cw.x + h.y * cw.y + h.z * cw.z + h.w * cw.w;
            }
        }
        #pragma unroll
        for (int r = 0; r < 4; r++) {
            float a0 = fmaxf(y[r][0], 0.f), a1 = fmaxf(y[r][1], 0.f);
            g_A[(size_t)(b0 + r) * 64 + lane]      = a0;
            g_A[(size_t)(b0 + r) * 64 + lane + 32] = a1;
            s0 += a0; q0 += a0 * a0;
            s1 += a1; q1 += a1 * a1;
        }
        __syncwarp();
    }
    atomicAdd(&sacc[lane],      s0); atomicAdd(&qacc[lane],      q0);
    atomicAdd(&sacc[lane + 32], s1); atomicAdd(&qacc[lane + 32], q1);
    __syncthreads();
    if (tid < 64) {
        atomicAdd(&g_stats[tid],      sacc[tid]);
        atomicAdd(&g_stats[64 + tid], qacc[tid]);
    }
}

// ===================== K4: finalize BN, fold into W2 =====================
__global__ void finalize_kernel(const float* __restrict__ gamma,
                                const float* __restrict__ beta,
                                const float* __restrict__ W2,
                                const float* __restrict__ b2) {
    __shared__ float red0[64], red1[64];
    int j = threadIdx.x;
    float mu  = g_stats[j]      * (1.f / BATCH);
    float var = g_stats[64 + j] * (1.f / BATCH) - mu * mu;
    float inv = rsqrtf(var + 1e-5f);
    float gsc = gamma[j] * inv;
    float w0 = W2[j], w1 = W2[64 + j];
    g_W2e[2 * j]     = w0 * gsc;
    g_W2e[2 * j + 1] = w1 * gsc;
    float c = beta[j] - mu * gsc;
    red0[j] = c * w0;
    red1[j] = c * w1;
    __syncthreads();
    if (j == 0) { float s = 0.f; for (int i = 0; i < 64; i++) s += red0[i]; g_be[0] = b2[0] + s; }
    if (j == 1) { float s = 0.f; for (int i = 0; i < 64; i++) s += red1[i]; g_be[1] = b2[1] + s; }
}

// ===================== K5: output = A @ W2e + be =====================
__global__ __launch_bounds__(256) void out_kernel(float* __restrict__ out) {
    __shared__ float w2s[128];
    __shared__ float bes[2];
    int tid = threadIdx.x;
    if (tid < 128) w2s[tid] = g_W2e[tid];
    if (tid < 2)   bes[tid] = g_be[tid];
    __syncthreads();
    int b = blockIdx.x * 256 + tid;
    const float4* ar = (const float4*)(g_A + (size_t)b * 64);
    float o0 = bes[0], o1 = bes[1];
    #pragma unroll
    for (int q = 0; q < 16; q++) {
        float4 v = ar[q];
        int j = q * 8;
        o0 += v.x * w2s[j]     + v.y * w2s[j + 2] + v.z * w2s[j + 4] + v.w * w2s[j + 6];
        o1 += v.x * w2s[j + 1] + v.y * w2s[j + 3] + v.z * w2s[j + 5] + v.w * w2s[j + 7];
    }
    ((float2*)out)[b] = make_float2(o0, o1);
}

// ===================== launcher =====================
extern "C" void kernel_launch(void* const* d_in, const int* in_sizes, int n_in,
                              void* d_out, int out_size) {
    const int*   n_id        = (const int*)  d_in[0];
    const float* memory      = (const float*)d_in[1];
    const int*   last_update = (const int*)  d_in[2];
    const int*   store_src   = (const int*)  d_in[3];
    const int*   store_dst   = (const int*)  d_in[4];
    const int*   store_t     = (const int*)  d_in[5];
    const float* store_msg   = (const float*)d_in[6];
    const float* time_w      = (const float*)d_in[7];
    const float* time_b      = (const float*)d_in[8];
    const float* W_ih        = (const float*)d_in[9];
    const float* b_ih        = (const float*)d_in[10];
    const float* W_hh        = (const float*)d_in[11];
    const float* b_hh        = (const float*)d_in[12];
    const float* W1          = (const float*)d_in[13];
    const float* b1          = (const float*)d_in[14];
    const float* gamma       = (const float*)d_in[15];
    const float* beta        = (const float*)d_in[16];
    const float* W2          = (const float*)d_in[17];
    const float* b2          = (const float*)d_in[18];
    float*       out         = (float*)d_out;

    cudaFuncSetAttribute(gemm_kernel, cudaFuncAttributeMaxDynamicSharedMemorySize, SMEM_TOT);

    prep_kernel<<<(NP * KP + 255) / 256, 256>>>(W_ih, W_hh, b_ih, b_hh);
    assemble_kernel<<<BATCH / 8, 256>>>(n_id, memory, last_update, store_src,
                                        store_dst, store_t, store_msg, time_w, time_b);
    gemm_kernel<<<dim3(BATCH / BMM, 5), 256, SMEM_TOT>>>();
    w1bn_kernel<<<BATCH / 64, 256>>>(W1, b1);
    finalize_kernel<<<1, 64>>>(gamma, beta, W2, b2);
    out_kernel<<<BATCH / 256, 256>>>(out);
}

// round 8
// speedup vs baseline: 3.4362x; 1.2045x over previous
#include <cuda_runtime.h>
#include <cuda_fp16.h>
#include <math.h>
#include <stdint.h>

#define BATCH   262144
#define DD      100
#define KP      448       // padded K (fp16 cols): 404 -> 448
#define NP      400       // interleaved gate rows: 100 quadruples (r,z,n,hn)
#define BMM     128
#define BNN     80
#define NCHUNK  7         // 448/64

// -------- device scratch --------
__device__ __half g_Xhi[(size_t)BATCH * KP];
__device__ __half g_Xlo[(size_t)BATCH * KP];   // only for exact-h reconstruction
__device__ __half g_Whi[(size_t)NP * KP];
__device__ float g_bq[NP];
__device__ float g_HN[(size_t)BATCH * DD];     // h_new fp32
__device__ float g_A [(size_t)BATCH * 64];
__device__ float g_stats[128];
__device__ float g_W2e[128];
__device__ float g_be[2];

__device__ __forceinline__ uint32_t smem_u32(const void* p) {
    uint32_t a;
    asm("{ .reg .u64 t; cvta.to.shared.u64 t, %1; cvt.u32.u64 %0, t; }" : "=r"(a) : "l"(p));
    return a;
}
#define LDSM4(r, a) asm volatile("ldmatrix.sync.aligned.m8n8.x4.shared.b16 {%0,%1,%2,%3}, [%4];" \
    : "=r"((r)[0]), "=r"((r)[1]), "=r"((r)[2]), "=r"((r)[3]) : "r"(a))
#define LDSM2(r, a) asm volatile("ldmatrix.sync.aligned.m8n8.x2.shared.b16 {%0,%1}, [%2];" \
    : "=r"((r)[0]), "=r"((r)[1]) : "r"(a))
#define MMA(c, a, b) asm volatile( \
    "mma.sync.aligned.m16n8k16.row.col.f32.f16.f16.f32 {%0,%1,%2,%3},{%4,%5,%6,%7},{%8,%9},{%0,%1,%2,%3};" \
    : "+f"((c)[0]), "+f"((c)[1]), "+f"((c)[2]), "+f"((c)[3])                                                \
    : "r"((a)[0]), "r"((a)[1]), "r"((a)[2]), "r"((a)[3]), "r"((b)[0]), "r"((b)[1]))
__device__ __forceinline__ void cpa16(uint32_t d, const void* s) {
    asm volatile("{ .reg .u64 g; cvta.to.global.u64 g, %1; cp.async.cg.shared.global [%0], [g], 16; }"
                 :: "r"(d), "l"(s));
}
#define CPA_COMMIT() asm volatile("cp.async.commit_group;" ::: "memory")

// smem stage: A_HI [0,16384), B_HI [16384,26624)
#define STAGE_SZ 26624
#define SBIAS    53248
#define SMEM_TOT 53632
// C staging (128 x 84 floats = 43008 B) reuses stage area

// ===================== K0: prep interleaved weights (fp16) =====================
__global__ __launch_bounds__(256) void prep_kernel(const float* __restrict__ W_ih,
                                                   const float* __restrict__ W_hh,
                                                   const float* __restrict__ b_ih,
                                                   const float* __restrict__ b_hh) {
    int idx = blockIdx.x * 256 + threadIdx.x;
    if (idx < NP * KP) {
        int r = idx / KP, k = idx % KP;
        int d = r >> 2, g = r & 3;
        float v = 0.f;
        if (g == 0) {
            if (k < 304)      v = W_ih[d * 304 + k];
            else if (k < 404) v = W_hh[d * 100 + (k - 304)];
        } else if (g == 1) {
            int rr = 100 + d;
            if (k < 304)      v = W_ih[rr * 304 + k];
            else if (k < 404) v = W_hh[rr * 100 + (k - 304)];
        } else if (g == 2) {
            if (k < 304)      v = W_ih[(200 + d) * 304 + k];
        } else {
            if (k >= 304 && k < 404) v = W_hh[(200 + d) * 100 + (k - 304)];
        }
        g_Whi[idx] = __float2half(v);
    }
    if (idx < NP) {
        int d = idx >> 2, g = idx & 3;
        float bv;
        if (g == 0)      bv = b_ih[d] + b_hh[d];
        else if (g == 1) bv = b_ih[100 + d] + b_hh[100 + d];
        else if (g == 2) bv = b_ih[200 + d];
        else             bv = b_hh[200 + d];
        g_bq[idx] = bv;
    }
    if (idx < 128) g_stats[idx] = 0.f;
}

// ===================== K1: gather + assemble X (fp16 hi/lo) =====================
__global__ __launch_bounds__(256) void assemble_kernel(const int*   __restrict__ n_id,
                                                       const float* __restrict__ memory,
                                                       const int*   __restrict__ last_update,
                                                       const int*   __restrict__ store_src,
                                                       const int*   __restrict__ store_dst,
                                                       const int*   __restrict__ store_t,
                                                       const float* __restrict__ store_msg,
                                                       const float* __restrict__ time_w,
                                                       const float* __restrict__ time_b) {
    int w = threadIdx.x >> 5, lane = threadIdx.x & 31;
    int b = blockIdx.x * 8 + w;
    int n   = n_id[b];
    int src = store_src[n];
    int dst = store_dst[n];
    float dt = (float)(store_t[n] - last_update[n]);
    const float* ms = memory + (size_t)src * DD;
    const float* md = memory + (size_t)dst * DD;
    const float* mn = memory + (size_t)n   * DD;
    __half* xh = g_Xhi + (size_t)b * KP;
    __half* xl = g_Xlo + (size_t)b * KP;
    #pragma unroll
    for (int c = lane; c < KP; c += 32) {
        float v;
        if (c < 100)      v = ms[c];
        else if (c < 200) v = md[c - 100];
        else if (c < 204) v = store_msg[(size_t)n * 4 + (c - 200)];
        else if (c < 304) {
            int j = c - 204;
            float arg = __fadd_rn(__fmul_rn(dt, time_w[j]), time_b[j]);  // no fma (match jax)
            v = cosf(arg);
        }
        else if (c < 404) v = mn[c - 304];
        else              v = 0.f;
        __half hi = __float2half(v);
        xh[c] = hi;
        xl[c] = __float2half(v - __half2float(hi));
    }
}

// ===================== K2: HMMA GEMM (fp16 single pass) + fused GRU ====
__global__ __launch_bounds__(256, 2) void gemm_kernel() {
    extern __shared__ char sm[];
    const uint32_t sb = smem_u32(sm);
    const int tid = threadIdx.x, wid = tid >> 5, lane = tid & 31;
    const int m0 = blockIdx.x * BMM;
    const int nt = blockIdx.y;
    const int n0 = nt * BNN;
    const int wm0 = (wid & 3) * 32;       // warp M offset
    const int wn0 = (wid >> 2) * 40;      // warp N offset

    if (tid < BNN) ((float*)(sm + SBIAS))[tid] = g_bq[n0 + tid];

    float c[2][5][4];
    #pragma unroll
    for (int i = 0; i < 2; i++)
        #pragma unroll
        for (int j = 0; j < 5; j++)
            #pragma unroll
            for (int q = 0; q < 4; q++) c[i][j][q] = 0.f;

    // -------- staging lambda (A: 1024, B: 640 x 16B cp.async) --------
    auto stage = [&](int ch, uint32_t base) {
        #pragma unroll 1
        for (int i = tid; i < 1664; i += 256) {
            uint32_t dst;
            const char* src;
            if (i < 1024) {
                int r = i >> 3, j = i & 7;
                src = (const char*)g_Xhi + (size_t)(m0 + r) * (KP * 2) + ch * 128 + j * 16;
                dst = base + r * 128 + ((j ^ (r & 7)) << 4);
            } else {
                int ii = i - 1024;
                int r = ii >> 3, j = ii & 7;
                src = (const char*)g_Whi + (size_t)(n0 + r) * (KP * 2) + ch * 128 + j * 16;
                dst = base + 16384 + r * 128 + ((j ^ (r & 7)) << 4);
            }
            cpa16(dst, src);
        }
        CPA_COMMIT();
    };

    stage(0, sb);   // prefetch chunk 0 -> stage 0

    for (int ch = 0; ch < NCHUNK; ch++) {
        if (ch < NCHUNK - 1) {
            stage(ch + 1, sb + ((ch + 1) & 1) * STAGE_SZ);
            asm volatile("cp.async.wait_group 1;" ::: "memory");
        } else {
            asm volatile("cp.async.wait_group 0;" ::: "memory");
        }
        __syncthreads();
        const uint32_t st = sb + (ch & 1) * STAGE_SZ;
        #pragma unroll
        for (int ks = 0; ks < 4; ks++) {
            uint32_t ah[2][4], bh[5][2];
            // A fragments
            int arow = wm0 + (lane & 7) + ((lane >> 3) & 1) * 8;
            int achk = 2 * ks + (lane >> 4);
            #pragma unroll
            for (int i = 0; i < 2; i++) {
                int r = arow + i * 16;
                LDSM4(ah[i], st + r * 128 + ((achk ^ (r & 7)) << 4));
            }
            // B fragments: j-pairs via LDSM4, tail block j=4 via LDSM2
            {
                int rr = wn0 + (lane & 7);
                int chk2 = 2 * ks + ((lane >> 3) & 1);
                #pragma unroll
                for (int jp = 0; jp < 2; jp++) {
                    int r = rr + (jp * 2 + (lane >> 4)) * 8;
                    uint32_t off = r * 128 + ((chk2 ^ (r & 7)) << 4);
                    uint32_t t4[4];
                    LDSM4(t4, st + 16384 + off);
                    bh[jp*2][0]   = t4[0]; bh[jp*2][1]   = t4[1];
                    bh[jp*2+1][0] = t4[2]; bh[jp*2+1][1] = t4[3];
                }
                int r = rr + 32;
                uint32_t off = r * 128 + ((chk2 ^ (r & 7)) << 4);
                LDSM2(bh[4], st + 16384 + off);
            }
            #pragma unroll
            for (int i = 0; i < 2; i++)
                #pragma unroll
                for (int j = 0; j < 5; j++)
                    MMA(c[i][j], ah[i], bh[j]);
        }
        __syncthreads();   // mma done before buffer (ch&1) is overwritten
    }

    // stage C (+bias) into smem: 128 x 84 floats
    float* Cs = (float*)sm;
    const float* sbias = (const float*)(sm + SBIAS);
    #pragma unroll
    for (int i = 0; i < 2; i++) {
        int r0 = wm0 + i * 16 + (lane >> 2);
        #pragma unroll
        for (int j = 0; j < 5; j++) {
            int cc = wn0 + j * 8 + 2 * (lane & 3);
            float bz0 = sbias[cc], bz1 = sbias[cc + 1];
            Cs[r0 * 84 + cc]           = c[i][j][0] + bz0;
            Cs[r0 * 84 + cc + 1]       = c[i][j][1] + bz1;
            Cs[(r0 + 8) * 84 + cc]     = c[i][j][2] + bz0;
            Cs[(r0 + 8) * 84 + cc + 1] = c[i][j][3] + bz1;
        }
    }
    __syncthreads();

    // fused GRU epilogue: 128 rows x 20 quadruples
    for (int g = tid; g < 128 * 20; g += 256) {
        int m = g / 20, dl = g % 20;
        float4 v = *(const float4*)&Cs[m * 84 + 4 * dl];
        int dg = nt * 20 + dl;
        int mg = m0 + m;
        float h = __half2float(g_Xhi[(size_t)mg * KP + 304 + dg]) +
                  __half2float(g_Xlo[(size_t)mg * KP + 304 + dg]);
        float rr = 1.f / (1.f + __expf(-v.x));
        float zz = 1.f / (1.f + __expf(-v.y));
        float nn = tanhf(v.z + rr * v.w);
        g_HN[(size_t)mg * DD + dg] = (1.f - zz) * nn + zz * h;
    }
}

// ===================== K3: A = relu(h_new @ W1^T + b1) + BN stats =====================
__global__ __launch_bounds__(256) void w1bn_kernel(const float* __restrict__ W1,
                                                   const float* __restrict__ b1) {
    __shared__ float W1s[64 * 100];
    __shared__ __align__(16) float hns[8][4][100];
    __shared__ float sacc[64], qacc[64];
    int tid = threadIdx.x;
    for (int i = tid; i < 6400; i += 256) W1s[i] = W1[i];
    if (tid < 64)       sacc[tid] = 0.f;
    else if (tid < 128) qacc[tid - 64] = 0.f;
    __syncthreads();

    int w = tid >> 5, lane = tid & 31;
    float b1a = b1[lane], b1b = b1[lane + 32];
    float s0 = 0.f, q0 = 0.f, s1 = 0.f, q1 = 0.f;
    const float4* wv0 = (const float4*)(W1s + lane * 100);
    const float4* wv1 = (const float4*)(W1s + (lane + 32) * 100);

    #pragma unroll
    for (int t4 = 0; t4 < 8; t4 += 4) {
        int b0 = blockIdx.x * 64 + w * 8 + t4;
        for (int i = lane; i < 100; i += 32)
            ((float4*)hns[w])[i] = ((const float4*)(g_HN + (size_t)b0 * DD))[i];
        __syncwarp();
        float y[4][2];
        #pragma unroll
        for (int r = 0; r < 4; r++) { y[r][0] = b1a; y[r][1] = b1b; }
        #pragma unroll
        for (int q = 0; q < 25; q++) {
            float4 a = wv0[q], cw = wv1[q];
            #pragma unroll
            for (int r = 0; r < 4; r++) {
                float4 h = ((const float4*)hns[w][r])[q];
                y[r][0] += h.x * a.x + h.y * a.y + h.z * a.z + h.w * a.w;
                y[r][1] += h.x * cw.x + h.y * cw.y + h.z * cw.z + h.w * cw.w;
            }
        }
        #pragma unroll
        for (int r = 0; r < 4; r++) {
            float a0 = fmaxf(y[r][0], 0.f), a1 = fmaxf(y[r][1], 0.f);
            g_A[(size_t)(b0 + r) * 64 + lane]      = a0;
            g_A[(size_t)(b0 + r) * 64 + lane + 32] = a1;
            s0 += a0; q0 += a0 * a0;
            s1 += a1; q1 += a1 * a1;
        }
        __syncwarp();
    }
    atomicAdd(&sacc[lane],      s0); atomicAdd(&qacc[lane],      q0);
    atomicAdd(&sacc[lane + 32], s1); atomicAdd(&qacc[lane + 32], q1);
    __syncthreads();
    if (tid < 64) {
        atomicAdd(&g_stats[tid],      sacc[tid]);
        atomicAdd(&g_stats[64 + tid], qacc[tid]);
    }
}

// ===================== K4: finalize BN, fold into W2 =====================
__global__ void finalize_kernel(const float* __restrict__ gamma,
                                const float* __restrict__ beta,
                                const float* __restrict__ W2,
                                const float* __restrict__ b2) {
    __shared__ float red0[64], red1[64];
    int j = threadIdx.x;
    float mu  = g_stats[j]      * (1.f / BATCH);
    float var = g_stats[64 + j] * (1.f / BATCH) - mu * mu;
    float inv = rsqrtf(var + 1e-5f);
    float gsc = gamma[j] * inv;
    float w0 = W2[j], w1 = W2[64 + j];
    g_W2e[2 * j]     = w0 * gsc;
    g_W2e[2 * j + 1] = w1 * gsc;
    float c = beta[j] - mu * gsc;
    red0[j] = c * w0;
    red1[j] = c * w1;
    __syncthreads();
    if (j == 0) { float s = 0.f; for (int i = 0; i < 64; i++) s += red0[i]; g_be[0] = b2[0] + s; }
    if (j == 1) { float s = 0.f; for (int i = 0; i < 64; i++) s += red1[i]; g_be[1] = b2[1] + s; }
}

// ===================== K5: output = A @ W2e + be =====================
__global__ __launch_bounds__(256) void out_kernel(float* __restrict__ out) {
    __shared__ float w2s[128];
    __shared__ float bes[2];
    int tid = threadIdx.x;
    if (tid < 128) w2s[tid] = g_W2e[tid];
    if (tid < 2)   bes[tid] = g_be[tid];
    __syncthreads();
    int b = blockIdx.x * 256 + tid;
    const float4* ar = (const float4*)(g_A + (size_t)b * 64);
    float o0 = bes[0], o1 = bes[1];
    #pragma unroll
    for (int q = 0; q < 16; q++) {
        float4 v = ar[q];
        int j = q * 8;
        o0 += v.x * w2s[j]     + v.y * w2s[j + 2] + v.z * w2s[j + 4] + v.w * w2s[j + 6];
        o1 += v.x * w2s[j + 1] + v.y * w2s[j + 3] + v.z * w2s[j + 5] + v.w * w2s[j + 7];
    }
    ((float2*)out)[b] = make_float2(o0, o1);
}

// ===================== launcher =====================
extern "C" void kernel_launch(void* const* d_in, const int* in_sizes, int n_in,
                              void* d_out, int out_size) {
    const int*   n_id        = (const int*)  d_in[0];
    const float* memory      = (const float*)d_in[1];
    const int*   last_update = (const int*)  d_in[2];
    const int*   store_src   = (const int*)  d_in[3];
    const int*   store_dst   = (const int*)  d_in[4];
    const int*   store_t     = (const int*)  d_in[5];
    const float* store_msg   = (const float*)d_in[6];
    const float* time_w      = (const float*)d_in[7];
    const float* time_b      = (const float*)d_in[8];
    const float* W_ih        = (const float*)d_in[9];
    const float* b_ih        = (const float*)d_in[10];
    const float* W_hh        = (const float*)d_in[11];
    const float* b_hh        = (const float*)d_in[12];
    const float* W1          = (const float*)d_in[13];
    const float* b1          = (const float*)d_in[14];
    const float* gamma       = (const float*)d_in[15];
    const float* beta        = (const float*)d_in[16];
    const float* W2          = (const float*)d_in[17];
    const float* b2          = (const float*)d_in[18];
    float*       out         = (float*)d_out;

    cudaFuncSetAttribute(gemm_kernel, cudaFuncAttributeMaxDynamicSharedMemorySize, SMEM_TOT);

    prep_kernel<<<(NP * KP + 255) / 256, 256>>>(W_ih, W_hh, b_ih, b_hh);
    assemble_kernel<<<BATCH / 8, 256>>>(n_id, memory, last_update, store_src,
                                        store_dst, store_t, store_msg, time_w, time_b);
    gemm_kernel<<<dim3(BATCH / BMM, 5), 256, SMEM_TOT>>>();
    w1bn_kernel<<<BATCH / 64, 256>>>(W1, b1);
    finalize_kernel<<<1, 64>>>(gamma, beta, W2, b2);
    out_kernel<<<BATCH / 256, 256>>>(out);
}

// round 9
// speedup vs baseline: 3.8077x; 1.1081x over previous
#include <cuda_runtime.h>
#include <cuda_fp16.h>
#include <math.h>
#include <stdint.h>

#define BATCH   262144
#define DD      100
#define KP      448       // padded K (fp16 cols): 404 -> 448
#define NP      400       // interleaved gate rows: 100 quadruples (r,z,n,hn)
#define BMM     128
#define BNN     80
#define NCHUNK  7         // 448/64
#define XLP     104       // packed X_lo width (h cols only)

// -------- device scratch --------
__device__ __half g_Xhi[(size_t)BATCH * KP];
__device__ __half g_Xlo[(size_t)BATCH * XLP];  // packed: cols 304..403 of X (for exact h)
__device__ __half g_Whi[(size_t)NP * KP];
__device__ float g_bq[NP];
__device__ float g_HN[(size_t)BATCH * DD];     // h_new fp32
__device__ float g_A [(size_t)BATCH * 64];
__device__ float g_stats[128];
__device__ float g_W2e[128];
__device__ float g_be[2];

__device__ __forceinline__ uint32_t smem_u32(const void* p) {
    uint32_t a;
    asm("{ .reg .u64 t; cvta.to.shared.u64 t, %1; cvt.u32.u64 %0, t; }" : "=r"(a) : "l"(p));
    return a;
}
#define LDSM4(r, a) asm volatile("ldmatrix.sync.aligned.m8n8.x4.shared.b16 {%0,%1,%2,%3}, [%4];" \
    : "=r"((r)[0]), "=r"((r)[1]), "=r"((r)[2]), "=r"((r)[3]) : "r"(a))
#define LDSM2(r, a) asm volatile("ldmatrix.sync.aligned.m8n8.x2.shared.b16 {%0,%1}, [%2];" \
    : "=r"((r)[0]), "=r"((r)[1]) : "r"(a))
#define MMA(c, a, b) asm volatile( \
    "mma.sync.aligned.m16n8k16.row.col.f32.f16.f16.f32 {%0,%1,%2,%3},{%4,%5,%6,%7},{%8,%9},{%0,%1,%2,%3};" \
    : "+f"((c)[0]), "+f"((c)[1]), "+f"((c)[2]), "+f"((c)[3])                                                \
    : "r"((a)[0]), "r"((a)[1]), "r"((a)[2]), "r"((a)[3]), "r"((b)[0]), "r"((b)[1]))
__device__ __forceinline__ void cpa16(uint32_t d, const void* s) {
    asm volatile("{ .reg .u64 g; cvta.to.global.u64 g, %1; cp.async.cg.shared.global [%0], [g], 16; }"
                 :: "r"(d), "l"(s));
}
#define CPA_COMMIT() asm volatile("cp.async.commit_group;" ::: "memory")

// smem: 3 stages of 26KB, then bias
// stage: A_HI [0,16384), B_HI [16384,26624)
#define STAGE_SZ 26624
#define SBIAS    79872
#define SMEM_TOT 80256
// C staging (128 x 84 floats = 43008 B) reuses stage area

// ===================== K0: prep interleaved weights (fp16) =====================
__global__ __launch_bounds__(256) void prep_kernel(const float* __restrict__ W_ih,
                                                   const float* __restrict__ W_hh,
                                                   const float* __restrict__ b_ih,
                                                   const float* __restrict__ b_hh) {
    int idx = blockIdx.x * 256 + threadIdx.x;
    if (idx < NP * KP) {
        int r = idx / KP, k = idx % KP;
        int d = r >> 2, g = r & 3;
        float v = 0.f;
        if (g == 0) {
            if (k < 304)      v = W_ih[d * 304 + k];
            else if (k < 404) v = W_hh[d * 100 + (k - 304)];
        } else if (g == 1) {
            int rr = 100 + d;
            if (k < 304)      v = W_ih[rr * 304 + k];
            else if (k < 404) v = W_hh[rr * 100 + (k - 304)];
        } else if (g == 2) {
            if (k < 304)      v = W_ih[(200 + d) * 304 + k];
        } else {
            if (k >= 304 && k < 404) v = W_hh[(200 + d) * 100 + (k - 304)];
        }
        g_Whi[idx] = __float2half(v);
    }
    if (idx < NP) {
        int d = idx >> 2, g = idx & 3;
        float bv;
        if (g == 0)      bv = b_ih[d] + b_hh[d];
        else if (g == 1) bv = b_ih[100 + d] + b_hh[100 + d];
        else if (g == 2) bv = b_ih[200 + d];
        else             bv = b_hh[200 + d];
        g_bq[idx] = bv;
    }
    if (idx < 128) g_stats[idx] = 0.f;
}

// ===================== K1: gather + assemble X (fp16 hi + packed lo) ============
__global__ __launch_bounds__(256) void assemble_kernel(const int*   __restrict__ n_id,
                                                       const float* __restrict__ memory,
                                                       const int*   __restrict__ last_update,
                                                       const int*   __restrict__ store_src,
                                                       const int*   __restrict__ store_dst,
                                                       const int*   __restrict__ store_t,
                                                       const float* __restrict__ store_msg,
                                                       const float* __restrict__ time_w,
                                                       const float* __restrict__ time_b) {
    int w = threadIdx.x >> 5, lane = threadIdx.x & 31;
    int b = blockIdx.x * 8 + w;
    int n   = n_id[b];
    int src = store_src[n];
    int dst = store_dst[n];
    float dt = (float)(store_t[n] - last_update[n]);
    const float* ms = memory + (size_t)src * DD;
    const float* md = memory + (size_t)dst * DD;
    const float* mn = memory + (size_t)n   * DD;
    __half* xh = g_Xhi + (size_t)b * KP;
    __half* xl = g_Xlo + (size_t)b * XLP;
    #pragma unroll
    for (int c = lane; c < KP; c += 32) {
        float v;
        if (c < 100)      v = ms[c];
        else if (c < 200) v = md[c - 100];
        else if (c < 204) v = store_msg[(size_t)n * 4 + (c - 200)];
        else if (c < 304) {
            int j = c - 204;
            float arg = __fadd_rn(__fmul_rn(dt, time_w[j]), time_b[j]);  // no fma (match jax)
            v = cosf(arg);
        }
        else if (c < 404) v = mn[c - 304];
        else              v = 0.f;
        __half hi = __float2half(v);
        xh[c] = hi;
        if (c >= 304 && c < 404)
            xl[c - 304] = __float2half(v - __half2float(hi));
    }
}

// ===================== K2: HMMA GEMM (fp16 single pass, 3-stage ring) + GRU ====
__global__ __launch_bounds__(256, 2) void gemm_kernel() {
    extern __shared__ char sm[];
    const uint32_t sb = smem_u32(sm);
    const int tid = threadIdx.x, wid = tid >> 5, lane = tid & 31;
    const int nt = blockIdx.x;            // N-tile fastest -> A reuse in L2
    const int m0 = blockIdx.y * BMM;
    const int n0 = nt * BNN;
    const int wm0 = (wid & 3) * 32;       // warp M offset
    const int wn0 = (wid >> 2) * 40;      // warp N offset

    if (tid < BNN) ((float*)(sm + SBIAS))[tid] = g_bq[n0 + tid];

    float c[2][5][4];
    #pragma unroll
    for (int i = 0; i < 2; i++)
        #pragma unroll
        for (int j = 0; j < 5; j++)
            #pragma unroll
            for (int q = 0; q < 4; q++) c[i][j][q] = 0.f;

    // -------- staging lambda (A: 1024, B: 640 x 16B cp.async) --------
    auto stage = [&](int ch, uint32_t base) {
        #pragma unroll 1
        for (int i = tid; i < 1664; i += 256) {
            uint32_t dst;
            const char* src;
            if (i < 1024) {
                int r = i >> 3, j = i & 7;
                src = (const char*)g_Xhi + (size_t)(m0 + r) * (KP * 2) + ch * 128 + j * 16;
                dst = base + r * 128 + ((j ^ (r & 7)) << 4);
            } else {
                int ii = i - 1024;
                int r = ii >> 3, j = ii & 7;
                src = (const char*)g_Whi + (size_t)(n0 + r) * (KP * 2) + ch * 128 + j * 16;
                dst = base + 16384 + r * 128 + ((j ^ (r & 7)) << 4);
            }
            cpa16(dst, src);
        }
        CPA_COMMIT();
    };

    stage(0, sb);
    stage(1, sb + STAGE_SZ);

    uint32_t stoff[3] = {0u, STAGE_SZ, 2u * STAGE_SZ};

    for (int ch = 0; ch < NCHUNK; ch++) {
        if (ch + 2 < NCHUNK) {
            stage(ch + 2, sb + stoff[(ch + 2) % 3]);
            asm volatile("cp.async.wait_group 2;" ::: "memory");
        } else if (ch + 2 == NCHUNK) {
            asm volatile("cp.async.wait_group 1;" ::: "memory");
        } else {
            asm volatile("cp.async.wait_group 0;" ::: "memory");
        }
        __syncthreads();
        const uint32_t st = sb + stoff[ch % 3];
        #pragma unroll
        for (int ks = 0; ks < 4; ks++) {
            uint32_t ah[2][4], bh[5][2];
            // A fragments
            int arow = wm0 + (lane & 7) + ((lane >> 3) & 1) * 8;
            int achk = 2 * ks + (lane >> 4);
            #pragma unroll
            for (int i = 0; i < 2; i++) {
                int r = arow + i * 16;
                LDSM4(ah[i], st + r * 128 + ((achk ^ (r & 7)) << 4));
            }
            // B fragments: j-pairs via LDSM4, tail block j=4 via LDSM2
            {
                int rr = wn0 + (lane & 7);
                int chk2 = 2 * ks + ((lane >> 3) & 1);
                #pragma unroll
                for (int jp = 0; jp < 2; jp++) {
                    int r = rr + (jp * 2 + (lane >> 4)) * 8;
                    uint32_t off = r * 128 + ((chk2 ^ (r & 7)) << 4);
                    uint32_t t4[4];
                    LDSM4(t4, st + 16384 + off);
                    bh[jp*2][0]   = t4[0]; bh[jp*2][1]   = t4[1];
                    bh[jp*2+1][0] = t4[2]; bh[jp*2+1][1] = t4[3];
                }
                int r = rr + 32;
                uint32_t off = r * 128 + ((chk2 ^ (r & 7)) << 4);
                LDSM2(bh[4], st + 16384 + off);
            }
            #pragma unroll
            for (int i = 0; i < 2; i++)
                #pragma unroll
                for (int j = 0; j < 5; j++)
                    MMA(c[i][j], ah[i], bh[j]);
        }
        __syncthreads();   // compute of ch done before its buffer is re-staged
    }

    // stage C (+bias) into smem: 128 x 84 floats
    float* Cs = (float*)sm;
    const float* sbias = (const float*)(sm + SBIAS);
    #pragma unroll
    for (int i = 0; i < 2; i++) {
        int r0 = wm0 + i * 16 + (lane >> 2);
        #pragma unroll
        for (int j = 0; j < 5; j++) {
            int cc = wn0 + j * 8 + 2 * (lane & 3);
            float bz0 = sbias[cc], bz1 = sbias[cc + 1];
            Cs[r0 * 84 + cc]           = c[i][j][0] + bz0;
            Cs[r0 * 84 + cc + 1]       = c[i][j][1] + bz1;
            Cs[(r0 + 8) * 84 + cc]     = c[i][j][2] + bz0;
            Cs[(r0 + 8) * 84 + cc + 1] = c[i][j][3] + bz1;
        }
    }
    __syncthreads();

    // fused GRU epilogue: 128 rows x 20 quadruples
    for (int g = tid; g < 128 * 20; g += 256) {
        int m = g / 20, dl = g % 20;
        float4 v = *(const float4*)&Cs[m * 84 + 4 * dl];
        int dg = nt * 20 + dl;
        int mg = m0 + m;
        float h = __half2float(g_Xhi[(size_t)mg * KP + 304 + dg]) +
                  __half2float(g_Xlo[(size_t)mg * XLP + dg]);
        float rr = 1.f / (1.f + __expf(-v.x));
        float zz = 1.f / (1.f + __expf(-v.y));
        float nn = tanhf(v.z + rr * v.w);
        g_HN[(size_t)mg * DD + dg] = (1.f - zz) * nn + zz * h;
    }
}

// ===================== K3: A = relu(h_new @ W1^T + b1) + BN stats =====================
__global__ __launch_bounds__(256) void w1bn_kernel(const float* __restrict__ W1,
                                                   const float* __restrict__ b1) {
    __shared__ float W1s[64 * 100];
    __shared__ __align__(16) float hns[8][4][100];
    __shared__ float sacc[64], qacc[64];
    int tid = threadIdx.x;
    for (int i = tid; i < 6400; i += 256) W1s[i] = W1[i];
    if (tid < 64)       sacc[tid] = 0.f;
    else if (tid < 128) qacc[tid - 64] = 0.f;
    __syncthreads();

    int w = tid >> 5, lane = tid & 31;
    float b1a = b1[lane], b1b = b1[lane + 32];
    float s0 = 0.f, q0 = 0.f, s1 = 0.f, q1 = 0.f;
    const float4* wv0 = (const float4*)(W1s + lane * 100);
    const float4* wv1 = (const float4*)(W1s + (lane + 32) * 100);

    #pragma unroll
    for (int t4 = 0; t4 < 8; t4 += 4) {
        int b0 = blockIdx.x * 64 + w * 8 + t4;
        for (int i = lane; i < 100; i += 32)
            ((float4*)hns[w])[i] = ((const float4*)(g_HN + (size_t)b0 * DD))[i];
        __syncwarp();
        float y[4][2];
        #pragma unroll
        for (int r = 0; r < 4; r++) { y[r][0] = b1a; y[r][1] = b1b; }
        #pragma unroll
        for (int q = 0; q < 25; q++) {
            float4 a = wv0[q], cw = wv1[q];
            #pragma unroll
            for (int r = 0; r < 4; r++) {
                float4 h = ((const float4*)hns[w][r])[q];
                y[r][0] += h.x * a.x + h.y * a.y + h.z * a.z + h.w * a.w;
                y[r][1] += h.x * cw.x + h.y * cw.y + h.z * cw.z + h.w * cw.w;
            }
        }
        #pragma unroll
        for (int r = 0; r < 4; r++) {
            float a0 = fmaxf(y[r][0], 0.f), a1 = fmaxf(y[r][1], 0.f);
            g_A[(size_t)(b0 + r) * 64 + lane]      = a0;
            g_A[(size_t)(b0 + r) * 64 + lane + 32] = a1;
            s0 += a0; q0 += a0 * a0;
            s1 += a1; q1 += a1 * a1;
        }
        __syncwarp();
    }
    atomicAdd(&sacc[lane],      s0); atomicAdd(&qacc[lane],      q0);
    atomicAdd(&sacc[lane + 32], s1); atomicAdd(&qacc[lane + 32], q1);
    __syncthreads();
    if (tid < 64) {
        atomicAdd(&g_stats[tid],      sacc[tid]);
        atomicAdd(&g_stats[64 + tid], qacc[tid]);
    }
}

// ===================== K4: finalize BN, fold into W2 =====================
__global__ void finalize_kernel(const float* __restrict__ gamma,
                                const float* __restrict__ beta,
                                const float* __restrict__ W2,
                                const float* __restrict__ b2) {
    __shared__ float red0[64], red1[64];
    int j = threadIdx.x;
    float mu  = g_stats[j]      * (1.f / BATCH);
    float var = g_stats[64 + j] * (1.f / BATCH) - mu * mu;
    float inv = rsqrtf(var + 1e-5f);
    float gsc = gamma[j] * inv;
    float w0 = W2[j], w1 = W2[64 + j];
    g_W2e[2 * j]     = w0 * gsc;
    g_W2e[2 * j + 1] = w1 * gsc;
    float c = beta[j] - mu * gsc;
    red0[j] = c * w0;
    red1[j] = c * w1;
    __syncthreads();
    if (j == 0) { float s = 0.f; for (int i = 0; i < 64; i++) s += red0[i]; g_be[0] = b2[0] + s; }
    if (j == 1) { float s = 0.f; for (int i = 0; i < 64; i++) s += red1[i]; g_be[1] = b2[1] + s; }
}

// ===================== K5: output = A @ W2e + be =====================
__global__ __launch_bounds__(256) void out_kernel(float* __restrict__ out) {
    __shared__ float w2s[128];
    __shared__ float bes[2];
    int tid = threadIdx.x;
    if (tid < 128) w2s[tid] = g_W2e[tid];
    if (tid < 2)   bes[tid] = g_be[tid];
    __syncthreads();
    int b = blockIdx.x * 256 + tid;
    const float4* ar = (const float4*)(g_A + (size_t)b * 64);
    float o0 = bes[0], o1 = bes[1];
    #pragma unroll
    for (int q = 0; q < 16; q++) {
        float4 v = ar[q];
        int j = q * 8;
        o0 += v.x * w2s[j]     + v.y * w2s[j + 2] + v.z * w2s[j + 4] + v.w * w2s[j + 6];
        o1 += v.x * w2s[j + 1] + v.y * w2s[j + 3] + v.z * w2s[j + 5] + v.w * w2s[j + 7];
    }
    ((float2*)out)[b] = make_float2(o0, o1);
}

// ===================== launcher =====================
extern "C" void kernel_launch(void* const* d_in, const int* in_sizes, int n_in,
                              void* d_out, int out_size) {
    const int*   n_id        = (const int*)  d_in[0];
    const float* memory      = (const float*)d_in[1];
    const int*   last_update = (const int*)  d_in[2];
    const int*   store_src   = (const int*)  d_in[3];
    const int*   store_dst   = (const int*)  d_in[4];
    const int*   store_t     = (const int*)  d_in[5];
    const float* store_msg   = (const float*)d_in[6];
    const float* time_w      = (const float*)d_in[7];
    const float* time_b      = (const float*)d_in[8];
    const float* W_ih        = (const float*)d_in[9];
    const float* b_ih        = (const float*)d_in[10];
    const float* W_hh        = (const float*)d_in[11];
    const float* b_hh        = (const float*)d_in[12];
    const float* W1          = (const float*)d_in[13];
    const float* b1          = (const float*)d_in[14];
    const float* gamma       = (const float*)d_in[15];
    const float* beta        = (const float*)d_in[16];
    const float* W2          = (const float*)d_in[17];
    const float* b2          = (const float*)d_in[18];
    float*       out         = (float*)d_out;

    cudaFuncSetAttribute(gemm_kernel, cudaFuncAttributeMaxDynamicSharedMemorySize, SMEM_TOT);

    prep_kernel<<<(NP * KP + 255) / 256, 256>>>(W_ih, W_hh, b_ih, b_hh);
    assemble_kernel<<<BATCH / 8, 256>>>(n_id, memory, last_update, store_src,
                                        store_dst, store_t, store_msg, time_w, time_b);
    gemm_kernel<<<dim3(5, BATCH / BMM), 256, SMEM_TOT>>>();
    w1bn_kernel<<<BATCH / 64, 256>>>(W1, b1);
    finalize_kernel<<<1, 64>>>(gamma, beta, W2, b2);
    out_kernel<<<BATCH / 256, 256>>>(out);
}

// round 10
// speedup vs baseline: 4.2496x; 1.1161x over previous
#include <cuda_runtime.h>
#include <cuda_fp16.h>
#include <math.h>
#include <stdint.h>

#define BATCH   262144
#define DD      100
#define KP      448       // padded K (fp16 cols): 404 -> 448
#define NP      400       // interleaved gate rows: 100 quadruples (r,z,n,hn)
#define BMM     128
#define BNN     80
#define NCHUNK  7         // 448/64
#define XLP     104       // packed X_lo width (h cols only)

// -------- device scratch --------
__device__ __half g_Xhi[(size_t)BATCH * KP];
__device__ __half g_Xlo[(size_t)BATCH * XLP];  // packed: cols 304..403 of X (for exact h)
__device__ __half g_Whi[(size_t)NP * KP];
__device__ __half g_W1h[64 * 128];             // W1 fp16, K padded to 128
__device__ float g_bq[NP];
__device__ __half g_HNh[(size_t)BATCH * 128];  // h_new fp16, 128-col padded (cols 100..127 stay 0)
__device__ float g_A [(size_t)BATCH * 64];
__device__ float g_stats[128];
__device__ float g_W2e[128];
__device__ float g_be[2];

__device__ __forceinline__ uint32_t smem_u32(const void* p) {
    uint32_t a;
    asm("{ .reg .u64 t; cvta.to.shared.u64 t, %1; cvt.u32.u64 %0, t; }" : "=r"(a) : "l"(p));
    return a;
}
#define LDSM4(r, a) asm volatile("ldmatrix.sync.aligned.m8n8.x4.shared.b16 {%0,%1,%2,%3}, [%4];" \
    : "=r"((r)[0]), "=r"((r)[1]), "=r"((r)[2]), "=r"((r)[3]) : "r"(a))
#define LDSM2(r, a) asm volatile("ldmatrix.sync.aligned.m8n8.x2.shared.b16 {%0,%1}, [%2];" \
    : "=r"((r)[0]), "=r"((r)[1]) : "r"(a))
#define MMA(c, a, b) asm volatile( \
    "mma.sync.aligned.m16n8k16.row.col.f32.f16.f16.f32 {%0,%1,%2,%3},{%4,%5,%6,%7},{%8,%9},{%0,%1,%2,%3};" \
    : "+f"((c)[0]), "+f"((c)[1]), "+f"((c)[2]), "+f"((c)[3])                                                \
    : "r"((a)[0]), "r"((a)[1]), "r"((a)[2]), "r"((a)[3]), "r"((b)[0]), "r"((b)[1]))
__device__ __forceinline__ void cpa16(uint32_t d, const void* s) {
    asm volatile("{ .reg .u64 g; cvta.to.global.u64 g, %1; cp.async.cg.shared.global [%0], [g], 16; }"
                 :: "r"(d), "l"(s));
}
#define CPA_COMMIT() asm volatile("cp.async.commit_group;" ::: "memory")

// gemm smem: 3 stages of 26KB, then bias
#define STAGE_SZ 26624
#define SBIAS    79872
#define SMEM_TOT 80256
// w1bn smem: A(HN) [0,32768), B(W1) [32768,49152), b1 [49152,49408), sacc/qacc
#define WSM_B1   49152
#define WSM_S    49408
#define WSM_Q    49664
#define WSM_TOT  49920

// ===================== K0: prep interleaved weights (fp16) =====================
__global__ __launch_bounds__(256) void prep_kernel(const float* __restrict__ W_ih,
                                                   const float* __restrict__ W_hh,
                                                   const float* __restrict__ b_ih,
                                                   const float* __restrict__ b_hh,
                                                   const float* __restrict__ W1) {
    int idx = blockIdx.x * 256 + threadIdx.x;
    if (idx < NP * KP) {
        int r = idx / KP, k = idx % KP;
        int d = r >> 2, g = r & 3;
        float v = 0.f;
        if (g == 0) {
            if (k < 304)      v = W_ih[d * 304 + k];
            else if (k < 404) v = W_hh[d * 100 + (k - 304)];
        } else if (g == 1) {
            int rr = 100 + d;
            if (k < 304)      v = W_ih[rr * 304 + k];
            else if (k < 404) v = W_hh[rr * 100 + (k - 304)];
        } else if (g == 2) {
            if (k < 304)      v = W_ih[(200 + d) * 304 + k];
        } else {
            if (k >= 304 && k < 404) v = W_hh[(200 + d) * 100 + (k - 304)];
        }
        g_Whi[idx] = __float2half(v);
    }
    if (idx < 64 * 128) {
        int n = idx >> 7, k = idx & 127;
        g_W1h[idx] = __float2half(k < 100 ? W1[n * 100 + k] : 0.f);
    }
    if (idx < NP) {
        int d = idx >> 2, g = idx & 3;
        float bv;
        if (g == 0)      bv = b_ih[d] + b_hh[d];
        else if (g == 1) bv = b_ih[100 + d] + b_hh[100 + d];
        else if (g == 2) bv = b_ih[200 + d];
        else             bv = b_hh[200 + d];
        g_bq[idx] = bv;
    }
    if (idx < 128) g_stats[idx] = 0.f;
}

// ===================== K1: gather + assemble X (fp16 hi + packed lo) ============
__global__ __launch_bounds__(256) void assemble_kernel(const int*   __restrict__ n_id,
                                                       const float* __restrict__ memory,
                                                       const int*   __restrict__ last_update,
                                                       const int*   __restrict__ store_src,
                                                       const int*   __restrict__ store_dst,
                                                       const int*   __restrict__ store_t,
                                                       const float* __restrict__ store_msg,
                                                       const float* __restrict__ time_w,
                                                       const float* __restrict__ time_b) {
    int w = threadIdx.x >> 5, lane = threadIdx.x & 31;
    int b = blockIdx.x * 8 + w;
    int n   = n_id[b];
    int src = store_src[n];
    int dst = store_dst[n];
    float dt = (float)(store_t[n] - last_update[n]);
    const float* ms = memory + (size_t)src * DD;
    const float* md = memory + (size_t)dst * DD;
    const float* mn = memory + (size_t)n   * DD;
    __half* xh = g_Xhi + (size_t)b * KP;
    __half* xl = g_Xlo + (size_t)b * XLP;
    #pragma unroll
    for (int c = lane; c < KP; c += 32) {
        float v;
        if (c < 100)      v = ms[c];
        else if (c < 200) v = md[c - 100];
        else if (c < 204) v = store_msg[(size_t)n * 4 + (c - 200)];
        else if (c < 304) {
            int j = c - 204;
            float arg = __fadd_rn(__fmul_rn(dt, time_w[j]), time_b[j]);  // no fma (match jax)
            v = cosf(arg);
        }
        else if (c < 404) v = mn[c - 304];
        else              v = 0.f;
        __half hi = __float2half(v);
        xh[c] = hi;
        if (c >= 304 && c < 404)
            xl[c - 304] = __float2half(v - __half2float(hi));
    }
}

// ===================== K2: HMMA GEMM (fp16 single pass, 3-stage ring) + GRU ====
__global__ __launch_bounds__(256, 2) void gemm_kernel() {
    extern __shared__ char sm[];
    const uint32_t sb = smem_u32(sm);
    const int tid = threadIdx.x, wid = tid >> 5, lane = tid & 31;
    const int nt = blockIdx.x;            // N-tile fastest -> A reuse in L2
    const int m0 = blockIdx.y * BMM;
    const int n0 = nt * BNN;
    const int wm0 = (wid & 3) * 32;       // warp M offset
    const int wn0 = (wid >> 2) * 40;      // warp N offset

    if (tid < BNN) ((float*)(sm + SBIAS))[tid] = g_bq[n0 + tid];

    float c[2][5][4];
    #pragma unroll
    for (int i = 0; i < 2; i++)
        #pragma unroll
        for (int j = 0; j < 5; j++)
            #pragma unroll
            for (int q = 0; q < 4; q++) c[i][j][q] = 0.f;

    auto stage = [&](int ch, uint32_t base) {
        #pragma unroll 1
        for (int i = tid; i < 1664; i += 256) {
            uint32_t dst;
            const char* src;
            if (i < 1024) {
                int r = i >> 3, j = i & 7;
                src = (const char*)g_Xhi + (size_t)(m0 + r) * (KP * 2) + ch * 128 + j * 16;
                dst = base + r * 128 + ((j ^ (r & 7)) << 4);
            } else {
                int ii = i - 1024;
                int r = ii >> 3, j = ii & 7;
                src = (const char*)g_Whi + (size_t)(n0 + r) * (KP * 2) + ch * 128 + j * 16;
                dst = base + 16384 + r * 128 + ((j ^ (r & 7)) << 4);
            }
            cpa16(dst, src);
        }
        CPA_COMMIT();
    };

    stage(0, sb);
    stage(1, sb + STAGE_SZ);

    uint32_t stoff[3] = {0u, STAGE_SZ, 2u * STAGE_SZ};

    for (int ch = 0; ch < NCHUNK; ch++) {
        if (ch + 2 < NCHUNK) {
            stage(ch + 2, sb + stoff[(ch + 2) % 3]);
            asm volatile("cp.async.wait_group 2;" ::: "memory");
        } else if (ch + 2 == NCHUNK) {
            asm volatile("cp.async.wait_group 1;" ::: "memory");
        } else {
            asm volatile("cp.async.wait_group 0;" ::: "memory");
        }
        __syncthreads();
        const uint32_t st = sb + stoff[ch % 3];
        #pragma unroll
        for (int ks = 0; ks < 4; ks++) {
            uint32_t ah[2][4], bh[5][2];
            int arow = wm0 + (lane & 7) + ((lane >> 3) & 1) * 8;
            int achk = 2 * ks + (lane >> 4);
            #pragma unroll
            for (int i = 0; i < 2; i++) {
                int r = arow + i * 16;
                LDSM4(ah[i], st + r * 128 + ((achk ^ (r & 7)) << 4));
            }
            {
                int rr = wn0 + (lane & 7);
                int chk2 = 2 * ks + ((lane >> 3) & 1);
                #pragma unroll
                for (int jp = 0; jp < 2; jp++) {
                    int r = rr + (jp * 2 + (lane >> 4)) * 8;
                    uint32_t off = r * 128 + ((chk2 ^ (r & 7)) << 4);
                    uint32_t t4[4];
                    LDSM4(t4, st + 16384 + off);
                    bh[jp*2][0]   = t4[0]; bh[jp*2][1]   = t4[1];
                    bh[jp*2+1][0] = t4[2]; bh[jp*2+1][1] = t4[3];
                }
                int r = rr + 32;
                uint32_t off = r * 128 + ((chk2 ^ (r & 7)) << 4);
                LDSM2(bh[4], st + 16384 + off);
            }
            #pragma unroll
            for (int i = 0; i < 2; i++)
                #pragma unroll
                for (int j = 0; j < 5; j++)
                    MMA(c[i][j], ah[i], bh[j]);
        }
        __syncthreads();
    }

    // stage C (+bias) into smem: 128 x 84 floats
    float* Cs = (float*)sm;
    const float* sbias = (const float*)(sm + SBIAS);
    #pragma unroll
    for (int i = 0; i < 2; i++) {
        int r0 = wm0 + i * 16 + (lane >> 2);
        #pragma unroll
        for (int j = 0; j < 5; j++) {
            int cc = wn0 + j * 8 + 2 * (lane & 3);
            float bz0 = sbias[cc], bz1 = sbias[cc + 1];
            Cs[r0 * 84 + cc]           = c[i][j][0] + bz0;
            Cs[r0 * 84 + cc + 1]       = c[i][j][1] + bz1;
            Cs[(r0 + 8) * 84 + cc]     = c[i][j][2] + bz0;
            Cs[(r0 + 8) * 84 + cc + 1] = c[i][j][3] + bz1;
        }
    }
    __syncthreads();

    // fused GRU epilogue: 128 rows x 20 quadruples -> fp16 h_new
    for (int g = tid; g < 128 * 20; g += 256) {
        int m = g / 20, dl = g % 20;
        float4 v = *(const float4*)&Cs[m * 84 + 4 * dl];
        int dg = nt * 20 + dl;
        int mg = m0 + m;
        float h = __half2float(g_Xhi[(size_t)mg * KP + 304 + dg]) +
                  __half2float(g_Xlo[(size_t)mg * XLP + dg]);
        float rr = 1.f / (1.f + __expf(-v.x));
        float zz = 1.f / (1.f + __expf(-v.y));
        float nn = tanhf(v.z + rr * v.w);
        g_HNh[(size_t)mg * 128 + dg] = __float2half((1.f - zz) * nn + zz * h);
    }
}

// ===================== K3: HMMA A = relu(HN @ W1^T + b1) + BN stats =============
__global__ __launch_bounds__(256) void w1bn_kernel(const float* __restrict__ b1) {
    extern __shared__ char wsm[];
    const uint32_t sb = smem_u32(wsm);
    const int tid = threadIdx.x, wid = tid >> 5, lane = tid & 31;
    const int m0 = blockIdx.x * 128;
    const int wm0 = (wid & 3) * 32;
    const int wn0 = (wid >> 2) * 32;
    float* b1s  = (float*)(wsm + WSM_B1);
    float* sacc = (float*)(wsm + WSM_S);
    float* qacc = (float*)(wsm + WSM_Q);
    if (tid < 64) { b1s[tid] = b1[tid]; sacc[tid] = 0.f; qacc[tid] = 0.f; }

    // stage: HN tile 2 chunks x 128 rows x 8, W1 2 chunks x 64 rows x 8
    #pragma unroll 1
    for (int i = tid; i < 3072; i += 256) {
        uint32_t dst;
        const char* src;
        if (i < 2048) {
            int ch = i >> 10, ii = i & 1023, r = ii >> 3, j = ii & 7;
            src = (const char*)g_HNh + (size_t)(m0 + r) * 256 + ch * 128 + j * 16;
            dst = sb + ch * 16384 + r * 128 + ((j ^ (r & 7)) << 4);
        } else {
            int ii = i - 2048;
            int ch = ii >> 9, i2 = ii & 511, r = i2 >> 3, j = i2 & 7;
            src = (const char*)g_W1h + (size_t)r * 256 + ch * 128 + j * 16;
            dst = sb + 32768 + ch * 8192 + r * 128 + ((j ^ (r & 7)) << 4);
        }
        cpa16(dst, src);
    }
    CPA_COMMIT();
    asm volatile("cp.async.wait_group 0;" ::: "memory");
    __syncthreads();

    float c[2][4][4];
    #pragma unroll
    for (int i = 0; i < 2; i++)
        #pragma unroll
        for (int j = 0; j < 4; j++)
            #pragma unroll
            for (int q = 0; q < 4; q++) c[i][j][q] = 0.f;

    #pragma unroll
    for (int ks = 0; ks < 8; ks++) {
        int ch = ks >> 2, kk = ks & 3;
        uint32_t ah[2][4], bh[4][2];
        int arow = wm0 + (lane & 7) + ((lane >> 3) & 1) * 8;
        int achk = 2 * kk + (lane >> 4);
        #pragma unroll
        for (int i = 0; i < 2; i++) {
            int r = arow + i * 16;
            LDSM4(ah[i], sb + ch * 16384 + r * 128 + ((achk ^ (r & 7)) << 4));
        }
        int rr = wn0 + (lane & 7);
        int chk2 = 2 * kk + ((lane >> 3) & 1);
        #pragma unroll
        for (int jp = 0; jp < 2; jp++) {
            int r = rr + (jp * 2 + (lane >> 4)) * 8;
            uint32_t off = r * 128 + ((chk2 ^ (r & 7)) << 4);
            uint32_t t4[4];
            LDSM4(t4, sb + 32768 + ch * 8192 + off);
            bh[jp*2][0]   = t4[0]; bh[jp*2][1]   = t4[1];
            bh[jp*2+1][0] = t4[2]; bh[jp*2+1][1] = t4[3];
        }
        #pragma unroll
        for (int i = 0; i < 2; i++)
            #pragma unroll
            for (int j = 0; j < 4; j++)
                MMA(c[i][j], ah[i], bh[j]);
    }

    // epilogue: relu + store + BN partial sums
    #pragma unroll
    for (int j = 0; j < 4; j++) {
        int col = wn0 + j * 8 + 2 * (lane & 3);
        float bz0 = b1s[col], bz1 = b1s[col + 1];
        float s0 = 0.f, q0 = 0.f, s1 = 0.f, q1 = 0.f;
        #pragma unroll
        for (int i = 0; i < 2; i++) {
            int row = m0 + wm0 + i * 16 + (lane >> 2);
            float a0 = fmaxf(c[i][j][0] + bz0, 0.f);
            float a1 = fmaxf(c[i][j][1] + bz1, 0.f);
            float a2 = fmaxf(c[i][j][2] + bz0, 0.f);
            float a3 = fmaxf(c[i][j][3] + bz1, 0.f);
            g_A[(size_t)row * 64 + col]           = a0;
            g_A[(size_t)row * 64 + col + 1]       = a1;
            g_A[(size_t)(row + 8) * 64 + col]     = a2;
            g_A[(size_t)(row + 8) * 64 + col + 1] = a3;
            s0 += a0 + a2; q0 += a0 * a0 + a2 * a2;
            s1 += a1 + a3; q1 += a1 * a1 + a3 * a3;
        }
        #pragma unroll
        for (int off = 4; off <= 16; off <<= 1) {
            s0 += __shfl_xor_sync(0xffffffff, s0, off);
            q0 += __shfl_xor_sync(0xffffffff, q0, off);
            s1 += __shfl_xor_sync(0xffffffff, s1, off);
            q1 += __shfl_xor_sync(0xffffffff, q1, off);
        }
        if (lane < 4) {
            atomicAdd(&sacc[col], s0); atomicAdd(&qacc[col], q0);
            atomicAdd(&sacc[col + 1], s1); atomicAdd(&qacc[col + 1], q1);
        }
    }
    __syncthreads();
    if (tid < 64) {
        atomicAdd(&g_stats[tid],      sacc[tid]);
        atomicAdd(&g_stats[64 + tid], qacc[tid]);
    }
}

// ===================== K4: finalize BN, fold into W2 =====================
__global__ void finalize_kernel(const float* __restrict__ gamma,
                                const float* __restrict__ beta,
                                const float* __restrict__ W2,
                                const float* __restrict__ b2) {
    __shared__ float red0[64], red1[64];
    int j = threadIdx.x;
    float mu  = g_stats[j]      * (1.f / BATCH);
    float var = g_stats[64 + j] * (1.f / BATCH) - mu * mu;
    float inv = rsqrtf(var + 1e-5f);
    float gsc = gamma[j] * inv;
    float w0 = W2[j], w1 = W2[64 + j];
    g_W2e[2 * j]     = w0 * gsc;
    g_W2e[2 * j + 1] = w1 * gsc;
    float c = beta[j] - mu * gsc;
    red0[j] = c * w0;
    red1[j] = c * w1;
    __syncthreads();
    if (j == 0) { float s = 0.f; for (int i = 0; i < 64; i++) s += red0[i]; g_be[0] = b2[0] + s; }
    if (j == 1) { float s = 0.f; for (int i = 0; i < 64; i++) s += red1[i]; g_be[1] = b2[1] + s; }
}

// ===================== K5: output = A @ W2e + be =====================
__global__ __launch_bounds__(256) void out_kernel(float* __restrict__ out) {
    __shared__ float w2s[128];
    __shared__ float bes[2];
    int tid = threadIdx.x;
    if (tid < 128) w2s[tid] = g_W2e[tid];
    if (tid < 2)   bes[tid] = g_be[tid];
    __syncthreads();
    int b = blockIdx.x * 256 + tid;
    const float4* ar = (const float4*)(g_A + (size_t)b * 64);
    float o0 = bes[0], o1 = bes[1];
    #pragma unroll
    for (int q = 0; q < 16; q++) {
        float4 v = ar[q];
        int j = q * 8;
        o0 += v.x * w2s[j]     + v.y * w2s[j + 2] + v.z * w2s[j + 4] + v.w * w2s[j + 6];
        o1 += v.x * w2s[j + 1] + v.y * w2s[j + 3] + v.z * w2s[j + 5] + v.w * w2s[j + 7];
    }
    ((float2*)out)[b] = make_float2(o0, o1);
}

// ===================== launcher =====================
extern "C" void kernel_launch(void* const* d_in, const int* in_sizes, int n_in,
                              void* d_out, int out_size) {
    const int*   n_id        = (const int*)  d_in[0];
    const float* memory      = (const float*)d_in[1];
    const int*   last_update = (const int*)  d_in[2];
    const int*   store_src   = (const int*)  d_in[3];
    const int*   store_dst   = (const int*)  d_in[4];
    const int*   store_t     = (const int*)  d_in[5];
    const float* store_msg   = (const float*)d_in[6];
    const float* time_w      = (const float*)d_in[7];
    const float* time_b      = (const float*)d_in[8];
    const float* W_ih        = (const float*)d_in[9];
    const float* b_ih        = (const float*)d_in[10];
    const float* W_hh        = (const float*)d_in[11];
    const float* b_hh        = (const float*)d_in[12];
    const float* W1          = (const float*)d_in[13];
    const float* b1          = (const float*)d_in[14];
    const float* gamma       = (const float*)d_in[15];
    const float* beta        = (const float*)d_in[16];
    const float* W2          = (const float*)d_in[17];
    const float* b2          = (const float*)d_in[18];
    float*       out         = (float*)d_out;

    cudaFuncSetAttribute(gemm_kernel, cudaFuncAttributeMaxDynamicSharedMemorySize, SMEM_TOT);
    cudaFuncSetAttribute(w1bn_kernel, cudaFuncAttributeMaxDynamicSharedMemorySize, WSM_TOT);

    prep_kernel<<<(NP * KP + 255) / 256, 256>>>(W_ih, W_hh, b_ih, b_hh, W1);
    assemble_kernel<<<BATCH / 8, 256>>>(n_id, memory, last_update, store_src,
                                        store_dst, store_t, store_msg, time_w, time_b);
    gemm_kernel<<<dim3(5, BATCH / BMM), 256, SMEM_TOT>>>();
    w1bn_kernel<<<BATCH / 128, 256, WSM_TOT>>>(b1);
    finalize_kernel<<<1, 64>>>(gamma, beta, W2, b2);
    out_kernel<<<BATCH / 256, 256>>>(out);
}

// round 11
// speedup vs baseline: 4.3374x; 1.0207x over previous
#include <cuda_runtime.h>
#include <cuda_fp16.h>
#include <math.h>
#include <stdint.h>

#define BATCH   262144
#define DD      100
#define KP      416       // padded K (fp16 cols): 404 -> 416 (last chunk = 32 real cols)
#define NP      400       // interleaved gate rows: 100 quadruples (r,z,n,hn)
#define BMM     128
#define BNN     80
#define NCHUNK  7         // 6 full 64-col chunks + 1 half (32-col) chunk
#define XLP     104       // packed X_lo width (h cols only)

// -------- device scratch --------
__device__ __half g_Xhi[(size_t)BATCH * KP];
__device__ __half g_Xlo[(size_t)BATCH * XLP];  // packed: cols 304..403 of X (for exact h)
__device__ __half g_Whi[(size_t)NP * KP];
__device__ __half g_W1h[64 * 128];             // W1 fp16, K padded to 128
__device__ float g_bq[NP];
__device__ __half g_HNh[(size_t)BATCH * 128];  // h_new fp16, 128-col padded (cols 100..127 stay 0)
__device__ float g_A [(size_t)BATCH * 64];
__device__ float g_stats[128];
__device__ float g_W2e[128];
__device__ float g_be[2];

__device__ __forceinline__ uint32_t smem_u32(const void* p) {
    uint32_t a;
    asm("{ .reg .u64 t; cvta.to.shared.u64 t, %1; cvt.u32.u64 %0, t; }" : "=r"(a) : "l"(p));
    return a;
}
#define LDSM4(r, a) asm volatile("ldmatrix.sync.aligned.m8n8.x4.shared.b16 {%0,%1,%2,%3}, [%4];" \
    : "=r"((r)[0]), "=r"((r)[1]), "=r"((r)[2]), "=r"((r)[3]) : "r"(a))
#define LDSM2(r, a) asm volatile("ldmatrix.sync.aligned.m8n8.x2.shared.b16 {%0,%1}, [%2];" \
    : "=r"((r)[0]), "=r"((r)[1]) : "r"(a))
#define MMA(c, a, b) asm volatile( \
    "mma.sync.aligned.m16n8k16.row.col.f32.f16.f16.f32 {%0,%1,%2,%3},{%4,%5,%6,%7},{%8,%9},{%0,%1,%2,%3};" \
    : "+f"((c)[0]), "+f"((c)[1]), "+f"((c)[2]), "+f"((c)[3])                                                \
    : "r"((a)[0]), "r"((a)[1]), "r"((a)[2]), "r"((a)[3]), "r"((b)[0]), "r"((b)[1]))
__device__ __forceinline__ void cpa16(uint32_t d, const void* s) {
    asm volatile("{ .reg .u64 g; cvta.to.global.u64 g, %1; cp.async.cg.shared.global [%0], [g], 16; }"
                 :: "r"(d), "l"(s));
}
#define CPA_COMMIT() asm volatile("cp.async.commit_group;" ::: "memory")

// gemm smem: 3 stages of 26KB, then bias
#define STAGE_SZ 26624
#define SBIAS    79872
#define SMEM_TOT 80256
// w1bn smem: A(HN) [0,32768), B(W1) [32768,49152), b1, sacc, qacc
#define WSM_B1   49152
#define WSM_S    49408
#define WSM_Q    49664
#define WSM_TOT  49920

// ===================== K0: prep interleaved weights (fp16) =====================
__global__ __launch_bounds__(256) void prep_kernel(const float* __restrict__ W_ih,
                                                   const float* __restrict__ W_hh,
                                                   const float* __restrict__ b_ih,
                                                   const float* __restrict__ b_hh,
                                                   const float* __restrict__ W1) {
    int idx = blockIdx.x * 256 + threadIdx.x;
    if (idx < NP * KP) {
        int r = idx / KP, k = idx % KP;
        int d = r >> 2, g = r & 3;
        float v = 0.f;
        if (g == 0) {
            if (k < 304)      v = W_ih[d * 304 + k];
            else if (k < 404) v = W_hh[d * 100 + (k - 304)];
        } else if (g == 1) {
            int rr = 100 + d;
            if (k < 304)      v = W_ih[rr * 304 + k];
            else if (k < 404) v = W_hh[rr * 100 + (k - 304)];
        } else if (g == 2) {
            if (k < 304)      v = W_ih[(200 + d) * 304 + k];
        } else {
            if (k >= 304 && k < 404) v = W_hh[(200 + d) * 100 + (k - 304)];
        }
        g_Whi[idx] = __float2half(v);
    }
    if (idx < 64 * 128) {
        int n = idx >> 7, k = idx & 127;
        g_W1h[idx] = __float2half(k < 100 ? W1[n * 100 + k] : 0.f);
    }
    if (idx < NP) {
        int d = idx >> 2, g = idx & 3;
        float bv;
        if (g == 0)      bv = b_ih[d] + b_hh[d];
        else if (g == 1) bv = b_ih[100 + d] + b_hh[100 + d];
        else if (g == 2) bv = b_ih[200 + d];
        else             bv = b_hh[200 + d];
        g_bq[idx] = bv;
    }
    if (idx < 128) g_stats[idx] = 0.f;
}

// ===================== K1: gather + assemble X (fp16 hi + packed lo) ============
__global__ __launch_bounds__(256) void assemble_kernel(const int*   __restrict__ n_id,
                                                       const float* __restrict__ memory,
                                                       const int*   __restrict__ last_update,
                                                       const int*   __restrict__ store_src,
                                                       const int*   __restrict__ store_dst,
                                                       const int*   __restrict__ store_t,
                                                       const float* __restrict__ store_msg,
                                                       const float* __restrict__ time_w,
                                                       const float* __restrict__ time_b) {
    int w = threadIdx.x >> 5, lane = threadIdx.x & 31;
    int b = blockIdx.x * 8 + w;
    int n   = n_id[b];
    int src = store_src[n];
    int dst = store_dst[n];
    float dt = (float)(store_t[n] - last_update[n]);
    const float* ms = memory + (size_t)src * DD;
    const float* md = memory + (size_t)dst * DD;
    const float* mn = memory + (size_t)n   * DD;
    __half* xh = g_Xhi + (size_t)b * KP;
    __half* xl = g_Xlo + (size_t)b * XLP;
    #pragma unroll
    for (int c = lane; c < KP; c += 32) {
        float v;
        if (c < 100)      v = ms[c];
        else if (c < 200) v = md[c - 100];
        else if (c < 204) v = store_msg[(size_t)n * 4 + (c - 200)];
        else if (c < 304) {
            int j = c - 204;
            float arg = __fadd_rn(__fmul_rn(dt, time_w[j]), time_b[j]);  // no fma (match jax)
            v = cosf(arg);
        }
        else if (c < 404) v = mn[c - 304];
        else              v = 0.f;
        __half hi = __float2half(v);
        xh[c] = hi;
        if (c >= 304 && c < 404)
            xl[c - 304] = __float2half(v - __half2float(hi));
    }
}

// ===================== K2: HMMA GEMM (fp16, 3-stage, single-sync) + GRU ====
__global__ __launch_bounds__(256, 2) void gemm_kernel() {
    extern __shared__ char sm[];
    const uint32_t sb = smem_u32(sm);
    const int tid = threadIdx.x, wid = tid >> 5, lane = tid & 31;
    const int nt = blockIdx.x;            // N-tile fastest -> A reuse in L2
    const int m0 = blockIdx.y * BMM;
    const int n0 = nt * BNN;
    const int wm0 = (wid & 3) * 32;       // warp M offset
    const int wn0 = (wid >> 2) * 40;      // warp N offset

    if (tid < BNN) ((float*)(sm + SBIAS))[tid] = g_bq[n0 + tid];

    float c[2][5][4];
    #pragma unroll
    for (int i = 0; i < 2; i++)
        #pragma unroll
        for (int j = 0; j < 5; j++)
            #pragma unroll
            for (int q = 0; q < 4; q++) c[i][j][q] = 0.f;

    // stage: chunk ch (64 cols; ch 6 only 32 real cols -> j<4)
    auto stage = [&](int ch, uint32_t base) {
        #pragma unroll 1
        for (int i = tid; i < 1664; i += 256) {
            int j = i & 7;
            if (ch == 6 && j >= 4) continue;   // cols 416+ don't exist
            uint32_t dst;
            const char* src;
            if (i < 1024) {
                int r = i >> 3;
                src = (const char*)g_Xhi + (size_t)(m0 + r) * (KP * 2) + ch * 128 + j * 16;
                dst = base + r * 128 + ((j ^ (r & 7)) << 4);
            } else {
                int r = (i - 1024) >> 3;
                src = (const char*)g_Whi + (size_t)(n0 + r) * (KP * 2) + ch * 128 + j * 16;
                dst = base + 16384 + r * 128 + ((j ^ (r & 7)) << 4);
            }
            cpa16(dst, src);
        }
        CPA_COMMIT();
    };

    stage(0, sb);
    stage(1, sb + STAGE_SZ);

    uint32_t stoff[3] = {0u, STAGE_SZ, 2u * STAGE_SZ};

    for (int ch = 0; ch < NCHUNK; ch++) {
        // ensure chunk ch's loads are complete (groups ch+1.. may be pending)
        if (ch < NCHUNK - 1) asm volatile("cp.async.wait_group 1;" ::: "memory");
        else                 asm volatile("cp.async.wait_group 0;" ::: "memory");
        __syncthreads();   // all warps past compute(ch-1); ch's data visible to all
        if (ch + 2 < NCHUNK) stage(ch + 2, sb + stoff[(ch + 2) % 3]);  // overlaps compute(ch)
        const uint32_t st = sb + stoff[ch % 3];
        const int nks = (ch == NCHUNK - 1) ? 2 : 4;
        for (int ks = 0; ks < nks; ks++) {
            uint32_t ah[2][4], bh[5][2];
            int arow = wm0 + (lane & 7) + ((lane >> 3) & 1) * 8;
            int achk = 2 * ks + (lane >> 4);
            #pragma unroll
            for (int i = 0; i < 2; i++) {
                int r = arow + i * 16;
                LDSM4(ah[i], st + r * 128 + ((achk ^ (r & 7)) << 4));
            }
            {
                int rr = wn0 + (lane & 7);
                int chk2 = 2 * ks + ((lane >> 3) & 1);
                #pragma unroll
                for (int jp = 0; jp < 2; jp++) {
                    int r = rr + (jp * 2 + (lane >> 4)) * 8;
                    uint32_t off = r * 128 + ((chk2 ^ (r & 7)) << 4);
                    uint32_t t4[4];
                    LDSM4(t4, st + 16384 + off);
                    bh[jp*2][0]   = t4[0]; bh[jp*2][1]   = t4[1];
                    bh[jp*2+1][0] = t4[2]; bh[jp*2+1][1] = t4[3];
                }
                int r = rr + 32;
                uint32_t off = r * 128 + ((chk2 ^ (r & 7)) << 4);
                LDSM2(bh[4], st + 16384 + off);
            }
            #pragma unroll
            for (int i = 0; i < 2; i++)
                #pragma unroll
                for (int j = 0; j < 5; j++)
                    MMA(c[i][j], ah[i], bh[j]);
        }
    }
    __syncthreads();   // last compute done before smem reuse for C staging

    // stage C (+bias) into smem: 128 x 84 floats
    float* Cs = (float*)sm;
    const float* sbias = (const float*)(sm + SBIAS);
    #pragma unroll
    for (int i = 0; i < 2; i++) {
        int r0 = wm0 + i * 16 + (lane >> 2);
        #pragma unroll
        for (int j = 0; j < 5; j++) {
            int cc = wn0 + j * 8 + 2 * (lane & 3);
            float bz0 = sbias[cc], bz1 = sbias[cc + 1];
            Cs[r0 * 84 + cc]           = c[i][j][0] + bz0;
            Cs[r0 * 84 + cc + 1]       = c[i][j][1] + bz1;
            Cs[(r0 + 8) * 84 + cc]     = c[i][j][2] + bz0;
            Cs[(r0 + 8) * 84 + cc + 1] = c[i][j][3] + bz1;
        }
    }
    __syncthreads();

    // fused GRU epilogue: 128 rows x 20 quadruples -> fp16 h_new
    for (int g = tid; g < 128 * 20; g += 256) {
        int m = g / 20, dl = g % 20;
        float4 v = *(const float4*)&Cs[m * 84 + 4 * dl];
        int dg = nt * 20 + dl;
        int mg = m0 + m;
        float h = __half2float(g_Xhi[(size_t)mg * KP + 304 + dg]) +
                  __half2float(g_Xlo[(size_t)mg * XLP + dg]);
        float rr = 1.f / (1.f + __expf(-v.x));
        float zz = 1.f / (1.f + __expf(-v.y));
        float nn = tanhf(v.z + rr * v.w);
        g_HNh[(size_t)mg * 128 + dg] = __float2half((1.f - zz) * nn + zz * h);
    }
}

// ===================== K3: HMMA A = relu(HN @ W1^T + b1) + BN stats =============
__global__ __launch_bounds__(256) void w1bn_kernel(const float* __restrict__ b1) {
    extern __shared__ char wsm[];
    const uint32_t sb = smem_u32(wsm);
    const int tid = threadIdx.x, wid = tid >> 5, lane = tid & 31;
    const int m0 = blockIdx.x * 128;
    const int wm0 = (wid & 3) * 32;
    const int wn0 = (wid >> 2) * 32;
    float* b1s  = (float*)(wsm + WSM_B1);
    float* sacc = (float*)(wsm + WSM_S);
    float* qacc = (float*)(wsm + WSM_Q);
    if (tid < 64) { b1s[tid] = b1[tid]; sacc[tid] = 0.f; qacc[tid] = 0.f; }

    #pragma unroll 1
    for (int i = tid; i < 3072; i += 256) {
        uint32_t dst;
        const char* src;
        if (i < 2048) {
            int ch = i >> 10, ii = i & 1023, r = ii >> 3, j = ii & 7;
            src = (const char*)g_HNh + (size_t)(m0 + r) * 256 + ch * 128 + j * 16;
            dst = sb + ch * 16384 + r * 128 + ((j ^ (r & 7)) << 4);
        } else {
            int ii = i - 2048;
            int ch = ii >> 9, i2 = ii & 511, r = i2 >> 3, j = i2 & 7;
            src = (const char*)g_W1h + (size_t)r * 256 + ch * 128 + j * 16;
            dst = sb + 32768 + ch * 8192 + r * 128 + ((j ^ (r & 7)) << 4);
        }
        cpa16(dst, src);
    }
    CPA_COMMIT();
    asm volatile("cp.async.wait_group 0;" ::: "memory");
    __syncthreads();

    float c[2][4][4];
    #pragma unroll
    for (int i = 0; i < 2; i++)
        #pragma unroll
        for (int j = 0; j < 4; j++)
            #pragma unroll
            for (int q = 0; q < 4; q++) c[i][j][q] = 0.f;

    #pragma unroll
    for (int ks = 0; ks < 8; ks++) {
        int ch = ks >> 2, kk = ks & 3;
        uint32_t ah[2][4], bh[4][2];
        int arow = wm0 + (lane & 7) + ((lane >> 3) & 1) * 8;
        int achk = 2 * kk + (lane >> 4);
        #pragma unroll
        for (int i = 0; i < 2; i++) {
            int r = arow + i * 16;
            LDSM4(ah[i], sb + ch * 16384 + r * 128 + ((achk ^ (r & 7)) << 4));
        }
        int rr = wn0 + (lane & 7);
        int chk2 = 2 * kk + ((lane >> 3) & 1);
        #pragma unroll
        for (int jp = 0; jp < 2; jp++) {
            int r = rr + (jp * 2 + (lane >> 4)) * 8;
            uint32_t off = r * 128 + ((chk2 ^ (r & 7)) << 4);
            uint32_t t4[4];
            LDSM4(t4, sb + 32768 + ch * 8192 + off);
            bh[jp*2][0]   = t4[0]; bh[jp*2][1]   = t4[1];
            bh[jp*2+1][0] = t4[2]; bh[jp*2+1][1] = t4[3];
        }
        #pragma unroll
        for (int i = 0; i < 2; i++)
            #pragma unroll
            for (int j = 0; j < 4; j++)
                MMA(c[i][j], ah[i], bh[j]);
    }

    #pragma unroll
    for (int j = 0; j < 4; j++) {
        int col = wn0 + j * 8 + 2 * (lane & 3);
        float bz0 = b1s[col], bz1 = b1s[col + 1];
        float s0 = 0.f, q0 = 0.f, s1 = 0.f, q1 = 0.f;
        #pragma unroll
        for (int i = 0; i < 2; i++) {
            int row = m0 + wm0 + i * 16 + (lane >> 2);
            float a0 = fmaxf(c[i][j][0] + bz0, 0.f);
            float a1 = fmaxf(c[i][j][1] + bz1, 0.f);
            float a2 = fmaxf(c[i][j][2] + bz0, 0.f);
            float a3 = fmaxf(c[i][j][3] + bz1, 0.f);
            g_A[(size_t)row * 64 + col]           = a0;
            g_A[(size_t)row * 64 + col + 1]       = a1;
            g_A[(size_t)(row + 8) * 64 + col]     = a2;
            g_A[(size_t)(row + 8) * 64 + col + 1] = a3;
            s0 += a0 + a2; q0 += a0 * a0 + a2 * a2;
            s1 += a1 + a3; q1 += a1 * a1 + a3 * a3;
        }
        #pragma unroll
        for (int off = 4; off <= 16; off <<= 1) {
            s0 += __shfl_xor_sync(0xffffffff, s0, off);
            q0 += __shfl_xor_sync(0xffffffff, q0, off);
            s1 += __shfl_xor_sync(0xffffffff, s1, off);
            q1 += __shfl_xor_sync(0xffffffff, q1, off);
        }
        if (lane < 4) {
            atomicAdd(&sacc[col], s0); atomicAdd(&qacc[col], q0);
            atomicAdd(&sacc[col + 1], s1); atomicAdd(&qacc[col + 1], q1);
        }
    }
    __syncthreads();
    if (tid < 64) {
        atomicAdd(&g_stats[tid],      sacc[tid]);
        atomicAdd(&g_stats[64 + tid], qacc[tid]);
    }
}

// ===================== K4: finalize BN, fold into W2 =====================
__global__ void finalize_kernel(const float* __restrict__ gamma,
                                const float* __restrict__ beta,
                                const float* __restrict__ W2,
                                const float* __restrict__ b2) {
    __shared__ float red0[64], red1[64];
    int j = threadIdx.x;
    float mu  = g_stats[j]      * (1.f / BATCH);
    float var = g_stats[64 + j] * (1.f / BATCH) - mu * mu;
    float inv = rsqrtf(var + 1e-5f);
    float gsc = gamma[j] * inv;
    float w0 = W2[j], w1 = W2[64 + j];
    g_W2e[2 * j]     = w0 * gsc;
    g_W2e[2 * j + 1] = w1 * gsc;
    float c = beta[j] - mu * gsc;
    red0[j] = c * w0;
    red1[j] = c * w1;
    __syncthreads();
    if (j == 0) { float s = 0.f; for (int i = 0; i < 64; i++) s += red0[i]; g_be[0] = b2[0] + s; }
    if (j == 1) { float s = 0.f; for (int i = 0; i < 64; i++) s += red1[i]; g_be[1] = b2[1] + s; }
}

// ===================== K5: output = A @ W2e + be =====================
__global__ __launch_bounds__(256) void out_kernel(float* __restrict__ out) {
    __shared__ float w2s[128];
    __shared__ float bes[2];
    int tid = threadIdx.x;
    if (tid < 128) w2s[tid] = g_W2e[tid];
    if (tid < 2)   bes[tid] = g_be[tid];
    __syncthreads();
    int b = blockIdx.x * 256 + tid;
    const float4* ar = (const float4*)(g_A + (size_t)b * 64);
    float o0 = bes[0], o1 = bes[1];
    #pragma unroll
    for (int q = 0; q < 16; q++) {
        float4 v = ar[q];
        int j = q * 8;
        o0 += v.x * w2s[j]     + v.y * w2s[j + 2] + v.z * w2s[j + 4] + v.w * w2s[j + 6];
        o1 += v.x * w2s[j + 1] + v.y * w2s[j + 3] + v.z * w2s[j + 5] + v.w * w2s[j + 7];
    }
    ((float2*)out)[b] = make_float2(o0, o1);
}

// ===================== launcher =====================
extern "C" void kernel_launch(void* const* d_in, const int* in_sizes, int n_in,
                              void* d_out, int out_size) {
    const int*   n_id        = (const int*)  d_in[0];
    const float* memory      = (const float*)d_in[1];
    const int*   last_update = (const int*)  d_in[2];
    const int*   store_src   = (const int*)  d_in[3];
    const int*   store_dst   = (const int*)  d_in[4];
    const int*   store_t     = (const int*)  d_in[5];
    const float* store_msg   = (const float*)d_in[6];
    const float* time_w      = (const float*)d_in[7];
    const float* time_b      = (const float*)d_in[8];
    const float* W_ih        = (const float*)d_in[9];
    const float* b_ih        = (const float*)d_in[10];
    const float* W_hh        = (const float*)d_in[11];
    const float* b_hh        = (const float*)d_in[12];
    const float* W1          = (const float*)d_in[13];
    const float* b1          = (const float*)d_in[14];
    const float* gamma       = (const float*)d_in[15];
    const float* beta        = (const float*)d_in[16];
    const float* W2          = (const float*)d_in[17];
    const float* b2          = (const float*)d_in[18];
    float*       out         = (float*)d_out;

    cudaFuncSetAttribute(gemm_kernel, cudaFuncAttributeMaxDynamicSharedMemorySize, SMEM_TOT);
    cudaFuncSetAttribute(w1bn_kernel, cudaFuncAttributeMaxDynamicSharedMemorySize, WSM_TOT);

    prep_kernel<<<(NP * KP + 255) / 256, 256>>>(W_ih, W_hh, b_ih, b_hh, W1);
    assemble_kernel<<<BATCH / 8, 256>>>(n_id, memory, last_update, store_src,
                                        store_dst, store_t, store_msg, time_w, time_b);
    gemm_kernel<<<dim3(5, BATCH / BMM), 256, SMEM_TOT>>>();
    w1bn_kernel<<<BATCH / 128, 256, WSM_TOT>>>(b1);
    finalize_kernel<<<1, 64>>>(gamma, beta, W2, b2);
    out_kernel<<<BATCH / 256, 256>>>(out);
}